// round 2
// baseline (speedup 1.0000x reference)
#include <cuda_runtime.h>
#include <math.h>

#define TT    2048
#define HHD   2048
#define NHEADS 16
#define NKVH   4
#define HDIM   128
#define QSZ    2048
#define KVSZ   512
#define QKVN   3072
#define NEXP   8
#define II     4096
#define EPSV   1e-5f

// ---------------- device scratch (static, no allocations) ----------------
__device__ float g_xn  [TT * HHD];    // rmsnorm1 output
__device__ float g_qkv [TT * QKVN];   // qkv (rope+norm applied in place)
__device__ float g_att [TT * QSZ];    // attention output
__device__ float g_x2  [TT * HHD];    // residual after attention
__device__ float g_y   [TT * HHD];    // rmsnorm2 output
__device__ float g_g   [TT * II];     // gate / h buffer
__device__ float g_u   [TT * II];     // up buffer
__device__ int   g_expert[TT];
__device__ float g_gate  [TT];
__device__ int   g_cnt[NEXP];
__device__ int   g_off[NEXP];
__device__ int   g_cur[NEXP];
__device__ int   g_perm[TT];

// ---------------- rmsnorm ----------------
__global__ __launch_bounds__(256) void rmsnorm_kernel(
    const float* __restrict__ x, const float* __restrict__ w, float* __restrict__ o)
{
    int t = blockIdx.x, tid = threadIdx.x;
    const float* r = x + (size_t)t * HHD;
    float ss = 0.f;
    for (int j = tid; j < HHD; j += 256) { float v = r[j]; ss += v * v; }
    __shared__ float red[256];
    red[tid] = ss; __syncthreads();
    for (int s = 128; s > 0; s >>= 1) { if (tid < s) red[tid] += red[tid + s]; __syncthreads(); }
    float scale = rsqrtf(red[0] / (float)HHD + EPSV);
    float* out = o + (size_t)t * HHD;
    for (int j = tid; j < HHD; j += 256) out[j] = r[j] * scale * w[j];
}

// ---------------- generic fp32 tiled GEMM: C = A(MxK) * B(KxN) [+ Res] ----------------
__global__ __launch_bounds__(256) void gemm_kernel(
    const float* __restrict__ A, const float* __restrict__ B,
    float* __restrict__ C, int M, int N, int K, const float* __restrict__ Res)
{
    __shared__ float As[16][64];
    __shared__ float Bs[16][64];
    int bm = blockIdx.y * 64, bn = blockIdx.x * 64;
    int tid = threadIdx.x;
    int ar = tid >> 2, ac = (tid & 3) << 2;     // A: 64 rows x 16 cols, one float4/thread
    int br = tid >> 4, bc = (tid & 15) << 2;    // B: 16 rows x 64 cols
    int ty = tid >> 4, tx = tid & 15;
    float acc[4][4] = {};
    const float* Aptr = A + (size_t)(bm + ar) * K + ac;
    const float* Bptr = B + (size_t)br * N + bn + bc;
    for (int k0 = 0; k0 < K; k0 += 16) {
        float4 av = *(const float4*)(Aptr + k0);
        As[ac + 0][ar] = av.x; As[ac + 1][ar] = av.y;
        As[ac + 2][ar] = av.z; As[ac + 3][ar] = av.w;
        *(float4*)&Bs[br][bc] = *(const float4*)(Bptr + (size_t)k0 * N);
        __syncthreads();
#pragma unroll
        for (int k = 0; k < 16; k++) {
            float4 a = *(float4*)&As[k][ty << 2];
            float4 b = *(float4*)&Bs[k][tx << 2];
            acc[0][0] += a.x * b.x; acc[0][1] += a.x * b.y; acc[0][2] += a.x * b.z; acc[0][3] += a.x * b.w;
            acc[1][0] += a.y * b.x; acc[1][1] += a.y * b.y; acc[1][2] += a.y * b.z; acc[1][3] += a.y * b.w;
            acc[2][0] += a.z * b.x; acc[2][1] += a.z * b.y; acc[2][2] += a.z * b.z; acc[2][3] += a.z * b.w;
            acc[3][0] += a.w * b.x; acc[3][1] += a.w * b.y; acc[3][2] += a.w * b.z; acc[3][3] += a.w * b.w;
        }
        __syncthreads();
    }
#pragma unroll
    for (int i = 0; i < 4; i++) {
        size_t row = bm + (ty << 2) + i;
        float4 v = make_float4(acc[i][0], acc[i][1], acc[i][2], acc[i][3]);
        size_t idx = row * N + bn + (tx << 2);
        if (Res) { float4 r4 = *(const float4*)&Res[idx];
                   v.x += r4.x; v.y += r4.y; v.z += r4.z; v.w += r4.w; }
        *(float4*)&C[idx] = v;
    }
}

// ---------------- rope + q/k rmsnorm (in place on qkv) ----------------
__global__ __launch_bounds__(256) void ropenorm_kernel(
    float* __restrict__ qkv, const int* __restrict__ pos,
    const float* __restrict__ qw, const float* __restrict__ kw)
{
    int t = blockIdx.x, tid = threadIdx.x;
    float* row = qkv + (size_t)t * QKVN;
    float p = (float)pos[t];
    const float lgt = logf(500000.0f);
    __shared__ float red[256];
    __shared__ float sq, sk;

    // Q: 16 heads * 64 pairs = 1024 pairs
    float ss = 0.f;
    for (int idx = tid; idx < 1024; idx += 256) {
        int hh = idx >> 6, i = idx & 63;
        float inv = expf(-lgt * (float)i * (1.0f / 64.0f));
        float fr = p * inv, c = cosf(fr), s = sinf(fr);
        float x1 = row[hh * 128 + i], x2 = row[hh * 128 + 64 + i];
        float o1 = x1 * c - x2 * s, o2 = x2 * c + x1 * s;
        row[hh * 128 + i] = o1; row[hh * 128 + 64 + i] = o2;
        ss += o1 * o1 + o2 * o2;
    }
    red[tid] = ss; __syncthreads();
    for (int s2 = 128; s2 > 0; s2 >>= 1) { if (tid < s2) red[tid] += red[tid + s2]; __syncthreads(); }
    if (tid == 0) sq = rsqrtf(red[0] / (float)QSZ + EPSV);
    __syncthreads();

    // K: 4 heads * 64 pairs = 256 pairs
    float ssk = 0.f;
    {
        int hh = tid >> 6, i = tid & 63;
        float inv = expf(-lgt * (float)i * (1.0f / 64.0f));
        float fr = p * inv, c = cosf(fr), s = sinf(fr);
        float* kbase = row + QSZ;
        float x1 = kbase[hh * 128 + i], x2 = kbase[hh * 128 + 64 + i];
        float o1 = x1 * c - x2 * s, o2 = x2 * c + x1 * s;
        kbase[hh * 128 + i] = o1; kbase[hh * 128 + 64 + i] = o2;
        ssk = o1 * o1 + o2 * o2;
    }
    red[tid] = ssk; __syncthreads();
    for (int s2 = 128; s2 > 0; s2 >>= 1) { if (tid < s2) red[tid] += red[tid + s2]; __syncthreads(); }
    if (tid == 0) sk = rsqrtf(red[0] / (float)KVSZ + EPSV);
    __syncthreads();

    for (int j = tid; j < QSZ; j += 256) row[j] *= sq * qw[j];
    for (int j = tid; j < KVSZ; j += 256) row[QSZ + j] *= sk * kw[j];
}

// ---------------- flash attention (fp32, causal, GQA 16q/4kv) ----------------
#define QKSTR 132   // padded row stride for 128-dim tiles
#define SMEM_ATTN ((3 * 64 * QKSTR + 64 * 64) * 4)

__global__ __launch_bounds__(256) void attn_kernel(
    const float* __restrict__ qkv, float* __restrict__ O)
{
    extern __shared__ float sh[];
    float* Qs = sh;
    float* Ks = sh + 64 * QKSTR;
    float* Vs = sh + 2 * 64 * QKSTR;
    float* Ps = sh + 3 * 64 * QKSTR;

    int m0 = blockIdx.x * 64;
    int h  = blockIdx.y;
    int kvh = h >> 2;
    int tid = threadIdx.x, lane = tid & 31, w = tid >> 5;
    const float scl = 0.08838834764831845f;

    for (int i = tid; i < 2048; i += 256) {
        int r = i >> 5, c = (i & 31) << 2;
        *(float4*)&Qs[r * QKSTR + c] =
            *(const float4*)&qkv[(size_t)(m0 + r) * QKVN + h * HDIM + c];
    }

    float mrow[8], lrow[8], oacc[8][4];
#pragma unroll
    for (int r = 0; r < 8; r++) {
        mrow[r] = -1e30f; lrow[r] = 0.f;
        oacc[r][0] = oacc[r][1] = oacc[r][2] = oacc[r][3] = 0.f;
    }
    int d0 = lane << 2;

    for (int n0 = 0; n0 <= m0; n0 += 64) {
        __syncthreads();
        for (int i = tid; i < 2048; i += 256) {
            int r = i >> 5, c = (i & 31) << 2;
            *(float4*)&Ks[r * QKSTR + c] =
                *(const float4*)&qkv[(size_t)(n0 + r) * QKVN + QSZ + kvh * HDIM + c];
            *(float4*)&Vs[r * QKSTR + c] =
                *(const float4*)&qkv[(size_t)(n0 + r) * QKVN + QSZ + KVSZ + kvh * HDIM + c];
        }
        __syncthreads();

        // S = Q Kᵀ  (warp w owns rows 8w..8w+7; lane owns cols lane, lane+32)
        float s0[8] = {0.f,0.f,0.f,0.f,0.f,0.f,0.f,0.f};
        float s1[8] = {0.f,0.f,0.f,0.f,0.f,0.f,0.f,0.f};
        for (int k = 0; k < 128; k++) {
            float k0 = Ks[lane * QKSTR + k];
            float k1 = Ks[(lane + 32) * QKSTR + k];
#pragma unroll
            for (int r = 0; r < 8; r++) {
                float q = Qs[(w * 8 + r) * QKSTR + k];
                s0[r] += q * k0; s1[r] += q * k1;
            }
        }
        bool diag = (n0 + 63 > m0);  // tile touches the diagonal
#pragma unroll
        for (int r = 0; r < 8; r++) {
            int grow = m0 + w * 8 + r;
            float v0 = s0[r] * scl, v1 = s1[r] * scl;
            if (diag) {
                if (n0 + lane      > grow) v0 = -1e30f;
                if (n0 + lane + 32 > grow) v1 = -1e30f;
            }
            float tmax = fmaxf(v0, v1);
#pragma unroll
            for (int o = 16; o; o >>= 1) tmax = fmaxf(tmax, __shfl_xor_sync(~0u, tmax, o));
            float nm = fmaxf(mrow[r], tmax);
            float p0 = __expf(v0 - nm), p1 = __expf(v1 - nm);
            float corr = __expf(mrow[r] - nm);
            float psum = p0 + p1;
#pragma unroll
            for (int o = 16; o; o >>= 1) psum += __shfl_xor_sync(~0u, psum, o);
            lrow[r] = lrow[r] * corr + psum;
            mrow[r] = nm;
            oacc[r][0] *= corr; oacc[r][1] *= corr; oacc[r][2] *= corr; oacc[r][3] *= corr;
            Ps[(w * 8 + r) * 64 + lane]      = p0;
            Ps[(w * 8 + r) * 64 + lane + 32] = p1;
        }
        __syncwarp();
        for (int n = 0; n < 64; n++) {
            float4 v = *(float4*)&Vs[n * QKSTR + d0];
#pragma unroll
            for (int r = 0; r < 8; r++) {
                float p = Ps[(w * 8 + r) * 64 + n];
                oacc[r][0] += p * v.x; oacc[r][1] += p * v.y;
                oacc[r][2] += p * v.z; oacc[r][3] += p * v.w;
            }
        }
    }
#pragma unroll
    for (int r = 0; r < 8; r++) {
        float inv = 1.0f / lrow[r];
        float4 o = make_float4(oacc[r][0] * inv, oacc[r][1] * inv,
                               oacc[r][2] * inv, oacc[r][3] * inv);
        *(float4*)&O[(size_t)(m0 + w * 8 + r) * QSZ + h * HDIM + d0] = o;
    }
}

// ---------------- router / permutation ----------------
__global__ void zero_kernel()
{
    int i = threadIdx.x;
    if (i < NEXP) { g_cnt[i] = 0; g_cur[i] = 0; }
}

__global__ __launch_bounds__(256) void router_kernel(
    const float* __restrict__ y, const float* __restrict__ rw)
{
    int t = blockIdx.x, tid = threadIdx.x;
    const float* x = y + (size_t)t * HHD;
    float part[NEXP] = {};
    for (int k = tid; k < HHD; k += 256) {
        float xv = x[k];
        const float* r = rw + (size_t)k * NEXP;
#pragma unroll
        for (int e = 0; e < NEXP; e++) part[e] += xv * r[e];
    }
    __shared__ float red[256];
    __shared__ float logit[NEXP];
    for (int e = 0; e < NEXP; e++) {
        red[tid] = part[e]; __syncthreads();
        for (int s = 128; s > 0; s >>= 1) { if (tid < s) red[tid] += red[tid + s]; __syncthreads(); }
        if (tid == 0) logit[e] = red[0];
        __syncthreads();
    }
    if (tid == 0) {
        int am = 0; float mv = logit[0];
        for (int e = 1; e < NEXP; e++) if (logit[e] > mv) { mv = logit[e]; am = e; }
        g_expert[t] = am;
        g_gate[t]   = 1.0f / (1.0f + expf(-mv));
        atomicAdd(&g_cnt[am], 1);
    }
}

__global__ void scan_kernel()
{
    int s = 0;
    for (int e = 0; e < NEXP; e++) { g_off[e] = s; s += g_cnt[e]; }
}

__global__ void scatter_kernel()
{
    int t = blockIdx.x * 256 + threadIdx.x;
    if (t >= TT) return;
    int e = g_expert[t];
    int p = atomicAdd(&g_cur[e], 1);
    g_perm[g_off[e] + p] = t;
}

// ---------------- silu(g) * u -> g ----------------
__global__ __launch_bounds__(256) void silu_kernel(float* __restrict__ g, const float* __restrict__ u)
{
    int i = blockIdx.x * 256 + threadIdx.x;
    float x = g[i];
    g[i] = (x / (1.0f + __expf(-x))) * u[i];
}

// ---------------- grouped GEMM (gate/up): Cg[grouped] = Y[perm] * W[e] ----------------
__global__ __launch_bounds__(256) void gemm_grouped_gu(
    const float* __restrict__ Y, const float* __restrict__ W,
    float* __restrict__ Cg, int N, int K)
{
    int e = blockIdx.z;
    int cnt = g_cnt[e];
    int r0 = blockIdx.y * 64;
    if (r0 >= cnt) return;
    int base = g_off[e];
    const float* B = W + (size_t)e * K * N;

    __shared__ float As[16][64];
    __shared__ float Bs[16][64];
    int bn = blockIdx.x * 64;
    int tid = threadIdx.x;
    int ar = tid >> 2, ac = (tid & 3) << 2;
    int br = tid >> 4, bc = (tid & 15) << 2;
    int ty = tid >> 4, tx = tid & 15;
    float acc[4][4] = {};
    int rr = r0 + ar; if (rr >= cnt) rr = cnt - 1;
    int token = g_perm[base + rr];
    const float* Aptr = Y + (size_t)token * K + ac;
    const float* Bptr = B + (size_t)br * N + bn + bc;
    for (int k0 = 0; k0 < K; k0 += 16) {
        float4 av = *(const float4*)(Aptr + k0);
        As[ac + 0][ar] = av.x; As[ac + 1][ar] = av.y;
        As[ac + 2][ar] = av.z; As[ac + 3][ar] = av.w;
        *(float4*)&Bs[br][bc] = *(const float4*)(Bptr + (size_t)k0 * N);
        __syncthreads();
#pragma unroll
        for (int k = 0; k < 16; k++) {
            float4 a = *(float4*)&As[k][ty << 2];
            float4 b = *(float4*)&Bs[k][tx << 2];
            acc[0][0] += a.x * b.x; acc[0][1] += a.x * b.y; acc[0][2] += a.x * b.z; acc[0][3] += a.x * b.w;
            acc[1][0] += a.y * b.x; acc[1][1] += a.y * b.y; acc[1][2] += a.y * b.z; acc[1][3] += a.y * b.w;
            acc[2][0] += a.z * b.x; acc[2][1] += a.z * b.y; acc[2][2] += a.z * b.z; acc[2][3] += a.z * b.w;
            acc[3][0] += a.w * b.x; acc[3][1] += a.w * b.y; acc[3][2] += a.w * b.z; acc[3][3] += a.w * b.w;
        }
        __syncthreads();
    }
#pragma unroll
    for (int i = 0; i < 4; i++) {
        int rloc = (ty << 2) + i;
        if (r0 + rloc < cnt) {
            size_t grow = base + r0 + rloc;
            float4 v = make_float4(acc[i][0], acc[i][1], acc[i][2], acc[i][3]);
            *(float4*)&Cg[grow * N + bn + (tx << 2)] = v;
        }
    }
}

// ---------------- grouped GEMM down: out[tok] += gate[tok] * (Hg * Wd[e]) ----------------
__global__ __launch_bounds__(256) void gemm_grouped_down(
    const float* __restrict__ Hg, const float* __restrict__ Wd,
    float* __restrict__ Out, int N, int K)
{
    int e = blockIdx.z;
    int cnt = g_cnt[e];
    int r0 = blockIdx.y * 64;
    if (r0 >= cnt) return;
    int base = g_off[e];
    const float* B = Wd + (size_t)e * K * N;

    __shared__ float As[16][64];
    __shared__ float Bs[16][64];
    int bn = blockIdx.x * 64;
    int tid = threadIdx.x;
    int ar = tid >> 2, ac = (tid & 3) << 2;
    int br = tid >> 4, bc = (tid & 15) << 2;
    int ty = tid >> 4, tx = tid & 15;
    float acc[4][4] = {};
    int arow = base + r0 + ar; if (arow > TT - 1) arow = TT - 1;
    const float* Aptr = Hg + (size_t)arow * K + ac;
    const float* Bptr = B + (size_t)br * N + bn + bc;
    for (int k0 = 0; k0 < K; k0 += 16) {
        float4 av = *(const float4*)(Aptr + k0);
        As[ac + 0][ar] = av.x; As[ac + 1][ar] = av.y;
        As[ac + 2][ar] = av.z; As[ac + 3][ar] = av.w;
        *(float4*)&Bs[br][bc] = *(const float4*)(Bptr + (size_t)k0 * N);
        __syncthreads();
#pragma unroll
        for (int k = 0; k < 16; k++) {
            float4 a = *(float4*)&As[k][ty << 2];
            float4 b = *(float4*)&Bs[k][tx << 2];
            acc[0][0] += a.x * b.x; acc[0][1] += a.x * b.y; acc[0][2] += a.x * b.z; acc[0][3] += a.x * b.w;
            acc[1][0] += a.y * b.x; acc[1][1] += a.y * b.y; acc[1][2] += a.y * b.z; acc[1][3] += a.y * b.w;
            acc[2][0] += a.z * b.x; acc[2][1] += a.z * b.y; acc[2][2] += a.z * b.z; acc[2][3] += a.z * b.w;
            acc[3][0] += a.w * b.x; acc[3][1] += a.w * b.y; acc[3][2] += a.w * b.z; acc[3][3] += a.w * b.w;
        }
        __syncthreads();
    }
#pragma unroll
    for (int i = 0; i < 4; i++) {
        int rloc = (ty << 2) + i;
        if (r0 + rloc < cnt) {
            int tok = g_perm[base + r0 + rloc];
            float gt = g_gate[tok];
            size_t idx = (size_t)tok * N + bn + (tx << 2);
            float4 o = *(float4*)&Out[idx];
            o.x += gt * acc[i][0]; o.y += gt * acc[i][1];
            o.z += gt * acc[i][2]; o.w += gt * acc[i][3];
            *(float4*)&Out[idx] = o;
        }
    }
}

// ---------------- launcher ----------------
extern "C" void kernel_launch(void* const* d_in, const int* in_sizes, int n_in,
                              void* d_out, int out_size)
{
    const int*   positions = (const int*)  d_in[0];
    const float* hidden    = (const float*)d_in[1];
    const float* ln1       = (const float*)d_in[2];
    const float* ln2       = (const float*)d_in[3];
    const float* w_qkv     = (const float*)d_in[4];
    const float* w_o       = (const float*)d_in[5];
    const float* qnw       = (const float*)d_in[6];
    const float* knw       = (const float*)d_in[7];
    const float* rw        = (const float*)d_in[8];
    const float* wsg       = (const float*)d_in[9];
    const float* wsu       = (const float*)d_in[10];
    const float* wsd       = (const float*)d_in[11];
    const float* weg       = (const float*)d_in[12];
    const float* weu       = (const float*)d_in[13];
    const float* wed       = (const float*)d_in[14];
    float* out = (float*)d_out;

    void* p;
    cudaGetSymbolAddress(&p, g_xn);  float* xn  = (float*)p;
    cudaGetSymbolAddress(&p, g_qkv); float* qkv = (float*)p;
    cudaGetSymbolAddress(&p, g_att); float* att = (float*)p;
    cudaGetSymbolAddress(&p, g_x2);  float* x2  = (float*)p;
    cudaGetSymbolAddress(&p, g_y);   float* y   = (float*)p;
    cudaGetSymbolAddress(&p, g_g);   float* gg  = (float*)p;
    cudaGetSymbolAddress(&p, g_u);   float* uu  = (float*)p;

    cudaFuncSetAttribute(attn_kernel, cudaFuncAttributeMaxDynamicSharedMemorySize, SMEM_ATTN);

    // 1. x = rmsnorm(hidden, ln1)
    rmsnorm_kernel<<<TT, 256>>>(hidden, ln1, xn);
    // 2. qkv = x @ w_qkv
    gemm_kernel<<<dim3(QKVN / 64, TT / 64), 256>>>(xn, w_qkv, qkv, TT, QKVN, HHD, nullptr);
    // 3. rope + q/k rmsnorm in place
    ropenorm_kernel<<<TT, 256>>>(qkv, positions, qnw, knw);
    // 4. flash attention
    attn_kernel<<<dim3(TT / 64, NHEADS), 256, SMEM_ATTN>>>(qkv, att);
    // 5. x2 = hidden + attn @ w_o
    gemm_kernel<<<dim3(HHD / 64, TT / 64), 256>>>(att, w_o, x2, TT, HHD, QSZ, hidden);
    // 6. y = rmsnorm(x2, ln2)
    rmsnorm_kernel<<<TT, 256>>>(x2, ln2, y);
    // 7. router: expert idx + sigmoid gate + counts
    zero_kernel<<<1, 32>>>();
    router_kernel<<<TT, 256>>>(y, rw);
    scan_kernel<<<1, 1>>>();
    scatter_kernel<<<TT / 256, 256>>>();
    // 8. shared expert
    gemm_kernel<<<dim3(II / 64, TT / 64), 256>>>(y, wsg, gg, TT, II, HHD, nullptr);
    gemm_kernel<<<dim3(II / 64, TT / 64), 256>>>(y, wsu, uu, TT, II, HHD, nullptr);
    silu_kernel<<<(TT * II) / 256, 256>>>(gg, uu);
    gemm_kernel<<<dim3(HHD / 64, TT / 64), 256>>>(gg, wsd, out, TT, HHD, II, x2);
    // 9. routed experts (grouped by permutation)
    gemm_grouped_gu<<<dim3(II / 64, TT / 64, NEXP), 256>>>(y, weg, gg, II, HHD);
    gemm_grouped_gu<<<dim3(II / 64, TT / 64, NEXP), 256>>>(y, weu, uu, II, HHD);
    silu_kernel<<<(TT * II) / 256, 256>>>(gg, uu);
    gemm_grouped_down<<<dim3(HHD / 64, TT / 64, NEXP), 256>>>(gg, wed, out, HHD, II);
}

// round 4
// speedup vs baseline: 2.0196x; 2.0196x over previous
#include <cuda_runtime.h>
#include <math.h>
#include <stdint.h>

#define TT     2048
#define HHD    2048
#define NHEADS 16
#define HDIM   128
#define QSZ    2048
#define KVSZ   512
#define QKVN   3072
#define NEXP   8
#define II     4096
#define EPSV   1e-5f

// ---------------- device scratch ----------------
__device__ __align__(256) float g_xn  [TT * HHD];
__device__ __align__(256) float g_qkv [TT * QKVN];
__device__ __align__(256) float g_att [TT * QSZ];
__device__ __align__(256) float g_x2  [TT * HHD];
__device__ __align__(256) float g_y   [TT * HHD];
__device__ __align__(256) float g_g   [TT * II];
__device__ __align__(256) float g_u   [TT * II];
__device__ int   g_expert[TT];
__device__ float g_gate  [TT];
__device__ int   g_cnt[NEXP];
__device__ int   g_off[NEXP];
__device__ int   g_cur[NEXP];
__device__ int   g_perm[TT];
__device__ __align__(256) float g_wqkvT [QKVN * HHD];
__device__ __align__(256) float g_wqkvTl[QKVN * HHD];
__device__ __align__(256) float g_woT   [HHD * QSZ];
__device__ __align__(256) float g_woTl  [HHD * QSZ];
__device__ __align__(256) float g_wsgT  [II * HHD];
__device__ __align__(256) float g_wsuT  [II * HHD];
__device__ __align__(256) float g_wsdT  [HHD * II];
__device__ __align__(256) float g_wegT  [NEXP * II * HHD];
__device__ __align__(256) float g_weuT  [NEXP * II * HHD];
__device__ __align__(256) float g_wedT  [NEXP * HHD * II];

// ---------------- helpers ----------------
__device__ __forceinline__ uint32_t smem_u32(const void* p) {
    uint32_t a;
    asm("{ .reg .u64 t; cvta.to.shared.u64 t, %1; cvt.u32.u64 %0, t; }" : "=r"(a) : "l"(p));
    return a;
}
__device__ __forceinline__ uint32_t f2tf32(float x) {
    uint32_t r;
    asm("cvt.rna.tf32.f32 %0, %1;" : "=r"(r) : "f"(x));
    return r;
}
__device__ __forceinline__ void cpa16(uint32_t dst, const float* src) {
    asm volatile("cp.async.cg.shared.global [%0], [%1], 16;" :: "r"(dst), "l"(src) : "memory");
}
#define CP_COMMIT() asm volatile("cp.async.commit_group;" ::: "memory")
#define CP_WAIT1()  asm volatile("cp.async.wait_group 1;" ::: "memory")
#define CP_WAIT0()  asm volatile("cp.async.wait_group 0;" ::: "memory")

#define MMA_TF32(d, a, b0, b1) \
  asm volatile("mma.sync.aligned.m16n8k8.row.col.f32.tf32.tf32.f32 " \
    "{%0,%1,%2,%3}, {%4,%5,%6,%7}, {%8,%9}, {%0,%1,%2,%3};" \
    : "+f"((d)[0]), "+f"((d)[1]), "+f"((d)[2]), "+f"((d)[3]) \
    : "r"((a)[0]), "r"((a)[1]), "r"((a)[2]), "r"((a)[3]), "r"(b0), "r"(b1))

// ---------------- weight transpose kernels ----------------
// out[(c)*R + r] = rna(in[r*C + c]);  grid (C/32, R/32, batch)
__global__ __launch_bounds__(256) void transpose_tf32(
    const float* __restrict__ in, float* __restrict__ out, int R, int C)
{
    __shared__ float t[32][33];
    size_t off = (size_t)blockIdx.z * R * C;
    in += off; out += off;
    int c0 = blockIdx.x * 32, r0 = blockIdx.y * 32;
    int tx = threadIdx.x & 31, ty = threadIdx.x >> 5;
    for (int j = ty; j < 32; j += 8)
        t[j][tx] = in[(size_t)(r0 + j) * C + c0 + tx];
    __syncthreads();
    for (int j = ty; j < 32; j += 8)
        out[(size_t)(c0 + j) * R + r0 + tx] = __uint_as_float(f2tf32(t[tx][j]));
}

// split version: hi = rna(x), lo = rna(x - hi)
__global__ __launch_bounds__(256) void transpose_split(
    const float* __restrict__ in, float* __restrict__ hi, float* __restrict__ lo,
    int R, int C)
{
    __shared__ float t[32][33];
    int c0 = blockIdx.x * 32, r0 = blockIdx.y * 32;
    int tx = threadIdx.x & 31, ty = threadIdx.x >> 5;
    for (int j = ty; j < 32; j += 8)
        t[j][tx] = in[(size_t)(r0 + j) * C + c0 + tx];
    __syncthreads();
    for (int j = ty; j < 32; j += 8) {
        float x = t[tx][j];
        uint32_t h = f2tf32(x);
        float l = x - __uint_as_float(h);
        size_t o = (size_t)(c0 + j) * R + r0 + tx;
        hi[o] = __uint_as_float(h);
        lo[o] = __uint_as_float(f2tf32(l));
    }
}

// ---------------- tensor-core GEMM (mma.sync tf32) ----------------
// Tile: 128x128x32.  Smem per tile: [128 rows][36 floats] (A rows=m, B rows=n).
// MODE 0: dense C = A@B (+Res).  MODE 1: rows gathered via g_perm, C grouped.
// MODE 2: A grouped-contiguous, C[tok] += g_gate[tok]*acc.
// COMP: compensated tf32 (A split on the fly, B pre-split hi/lo): 3 mmas.
#define ASZ 4608            // floats per 128x36 tile

template<int MODE, bool COMP>
__global__ void __launch_bounds__(256) gemm_mma(
    const float* __restrict__ A, const float* __restrict__ BH,
    const float* __restrict__ BL, float* __restrict__ C,
    int M, int N, int K, const float* __restrict__ Res)
{
    constexpr int STG = COMP ? 4 * ASZ : 2 * ASZ;   // floats per stage
    int e = blockIdx.z;
    int cnt = M, base = 0;
    if (MODE) {
        cnt = g_cnt[e]; base = g_off[e];
        if ((int)blockIdx.y * 128 >= cnt) return;
        BH += (size_t)e * (size_t)N * K;
    }
    int bm = blockIdx.y * 128, bn = blockIdx.x * 128;
    int tid = threadIdx.x, lane = tid & 31, warp = tid >> 5;
    int wm = warp & 3, wn = warp >> 2;
    int g = lane >> 2, tig = lane & 3;

    extern __shared__ __align__(16) float smf[];
    uint32_t smb = smem_u32(smf);
    const uint32_t* SM = (const uint32_t*)smf;

    // loader setup: 4 chunks/thread; chunk idx -> row=idx>>3, 16B col=(idx&7)*4
    const float* aptr[4]; const float* bhp[4]; const float* blp[4];
    uint32_t offT[4];
#pragma unroll
    for (int i = 0; i < 4; i++) {
        int idx = tid + 256 * i;
        int r = idx >> 3, cc = idx & 7;
        int row;
        if (MODE == 1) { int rr = bm + r; if (rr >= cnt) rr = cnt - 1; row = g_perm[base + rr]; }
        else if (MODE == 2) { int rr = bm + r; if (rr >= cnt) rr = cnt - 1; row = base + rr; }
        else row = bm + r;
        aptr[i] = A + (size_t)row * K + cc * 4;
        bhp[i]  = BH + (size_t)(bn + r) * K + cc * 4;
        if (COMP) blp[i] = BL + (size_t)(bn + r) * K + cc * 4;
        offT[i] = (uint32_t)(r * 36 + cc * 4) * 4;
    }

    float4 areg[4];
    // ---- prologue: fill stage 0 ----
#pragma unroll
    for (int i = 0; i < 4; i++) areg[i] = *(const float4*)(aptr[i]);
#pragma unroll
    for (int i = 0; i < 4; i++) {
        cpa16(smb + ASZ * 4 + offT[i], bhp[i]);
        if (COMP) cpa16(smb + 3 * ASZ * 4 + offT[i], blp[i]);
    }
    CP_COMMIT();
#pragma unroll
    for (int i = 0; i < 4; i++) {
        uint32_t h0 = f2tf32(areg[i].x), h1 = f2tf32(areg[i].y),
                 h2 = f2tf32(areg[i].z), h3 = f2tf32(areg[i].w);
        asm volatile("st.shared.v4.b32 [%0], {%1,%2,%3,%4};"
                     :: "r"(smb + offT[i]), "r"(h0), "r"(h1), "r"(h2), "r"(h3) : "memory");
        if (COMP) {
            uint32_t l0 = f2tf32(areg[i].x - __uint_as_float(h0));
            uint32_t l1 = f2tf32(areg[i].y - __uint_as_float(h1));
            uint32_t l2 = f2tf32(areg[i].z - __uint_as_float(h2));
            uint32_t l3 = f2tf32(areg[i].w - __uint_as_float(h3));
            asm volatile("st.shared.v4.b32 [%0], {%1,%2,%3,%4};"
                         :: "r"(smb + 2 * ASZ * 4 + offT[i]), "r"(l0), "r"(l1), "r"(l2), "r"(l3) : "memory");
        }
    }

    float acc[2][8][4];
#pragma unroll
    for (int mt = 0; mt < 2; mt++)
#pragma unroll
        for (int nt = 0; nt < 8; nt++)
#pragma unroll
            for (int q = 0; q < 4; q++) acc[mt][nt][q] = 0.f;

    const int abase = (wm * 32 + g) * 36 + tig;
    const int bbase = (wn * 64 + g) * 36 + tig;
    const int KC = K / 32;

    for (int c = 0; c < KC; c++) {
        int s = c & 1;
        bool more = (c + 1 < KC);
        if (more) {
            uint32_t nb = smb + (uint32_t)(s ^ 1) * STG * 4;
#pragma unroll
            for (int i = 0; i < 4; i++) areg[i] = *(const float4*)(aptr[i] + (c + 1) * 32);
#pragma unroll
            for (int i = 0; i < 4; i++) {
                cpa16(nb + ASZ * 4 + offT[i], bhp[i] + (c + 1) * 32);
                if (COMP) cpa16(nb + 3 * ASZ * 4 + offT[i], blp[i] + (c + 1) * 32);
            }
            CP_COMMIT();
            CP_WAIT1();
        } else {
            CP_WAIT0();
        }
        __syncthreads();

        const uint32_t* AH = SM + s * STG;
        const uint32_t* BHs = AH + ASZ;
        const uint32_t* AL = AH + 2 * ASZ;
        const uint32_t* BLs = AH + 3 * ASZ;

#pragma unroll
        for (int ks = 0; ks < 4; ks++) {
            uint32_t ah[2][4], al[2][4];
#pragma unroll
            for (int mt = 0; mt < 2; mt++) {
                int a0 = abase + mt * 16 * 36 + ks * 8;
                ah[mt][0] = AH[a0];           ah[mt][1] = AH[a0 + 8 * 36];
                ah[mt][2] = AH[a0 + 4];       ah[mt][3] = AH[a0 + 8 * 36 + 4];
                if (COMP) {
                    al[mt][0] = AL[a0];       al[mt][1] = AL[a0 + 8 * 36];
                    al[mt][2] = AL[a0 + 4];   al[mt][3] = AL[a0 + 8 * 36 + 4];
                }
            }
#pragma unroll
            for (int nt = 0; nt < 8; nt++) {
                int b0i = bbase + nt * 8 * 36 + ks * 8;
                uint32_t b0 = BHs[b0i], b1 = BHs[b0i + 4];
#pragma unroll
                for (int mt = 0; mt < 2; mt++)
                    MMA_TF32(acc[mt][nt], ah[mt], b0, b1);
                if (COMP) {
                    uint32_t bl0 = BLs[b0i], bl1 = BLs[b0i + 4];
#pragma unroll
                    for (int mt = 0; mt < 2; mt++) {
                        MMA_TF32(acc[mt][nt], al[mt], b0, b1);
                        MMA_TF32(acc[mt][nt], ah[mt], bl0, bl1);
                    }
                }
            }
        }
        __syncthreads();

        if (more) {
            uint32_t nb = smb + (uint32_t)(s ^ 1) * STG * 4;
#pragma unroll
            for (int i = 0; i < 4; i++) {
                uint32_t h0 = f2tf32(areg[i].x), h1 = f2tf32(areg[i].y),
                         h2 = f2tf32(areg[i].z), h3 = f2tf32(areg[i].w);
                asm volatile("st.shared.v4.b32 [%0], {%1,%2,%3,%4};"
                             :: "r"(nb + offT[i]), "r"(h0), "r"(h1), "r"(h2), "r"(h3) : "memory");
                if (COMP) {
                    uint32_t l0 = f2tf32(areg[i].x - __uint_as_float(h0));
                    uint32_t l1 = f2tf32(areg[i].y - __uint_as_float(h1));
                    uint32_t l2 = f2tf32(areg[i].z - __uint_as_float(h2));
                    uint32_t l3 = f2tf32(areg[i].w - __uint_as_float(h3));
                    asm volatile("st.shared.v4.b32 [%0], {%1,%2,%3,%4};"
                                 :: "r"(nb + 2 * ASZ * 4 + offT[i]), "r"(l0), "r"(l1), "r"(l2), "r"(l3) : "memory");
                }
            }
        }
    }

    // ---- epilogue ----
#pragma unroll
    for (int mt = 0; mt < 2; mt++) {
        int mloc0 = wm * 32 + mt * 16 + g;        // local row (second = +8)
#pragma unroll
        for (int nt = 0; nt < 8; nt++) {
            int col = bn + wn * 64 + nt * 8 + 2 * tig;
            float* d = acc[mt][nt];
            if (MODE == 0) {
                size_t i0 = (size_t)(bm + mloc0) * N + col;
                size_t i1 = (size_t)(bm + mloc0 + 8) * N + col;
                float2 v0 = make_float2(d[0], d[1]);
                float2 v1 = make_float2(d[2], d[3]);
                if (Res) {
                    float2 r0 = *(const float2*)&Res[i0];
                    float2 r1 = *(const float2*)&Res[i1];
                    v0.x += r0.x; v0.y += r0.y; v1.x += r1.x; v1.y += r1.y;
                }
                *(float2*)&C[i0] = v0;
                *(float2*)&C[i1] = v1;
            } else if (MODE == 1) {
                if (bm + mloc0 < cnt) {
                    size_t i0 = (size_t)(base + bm + mloc0) * N + col;
                    *(float2*)&C[i0] = make_float2(d[0], d[1]);
                }
                if (bm + mloc0 + 8 < cnt) {
                    size_t i1 = (size_t)(base + bm + mloc0 + 8) * N + col;
                    *(float2*)&C[i1] = make_float2(d[2], d[3]);
                }
            } else {
                if (bm + mloc0 < cnt) {
                    int tok = g_perm[base + bm + mloc0];
                    float gt = g_gate[tok];
                    size_t i0 = (size_t)tok * N + col;
                    float2 o = *(const float2*)&C[i0];
                    o.x += gt * d[0]; o.y += gt * d[1];
                    *(float2*)&C[i0] = o;
                }
                if (bm + mloc0 + 8 < cnt) {
                    int tok = g_perm[base + bm + mloc0 + 8];
                    float gt = g_gate[tok];
                    size_t i1 = (size_t)tok * N + col;
                    float2 o = *(const float2*)&C[i1];
                    o.x += gt * d[2]; o.y += gt * d[3];
                    *(float2*)&C[i1] = o;
                }
            }
        }
    }
}

// ---------------- rmsnorm ----------------
__global__ __launch_bounds__(256) void rmsnorm_kernel(
    const float* __restrict__ x, const float* __restrict__ w, float* __restrict__ o)
{
    int t = blockIdx.x, tid = threadIdx.x;
    const float* r = x + (size_t)t * HHD;
    float ss = 0.f;
    for (int j = tid; j < HHD; j += 256) { float v = r[j]; ss += v * v; }
    __shared__ float red[256];
    red[tid] = ss; __syncthreads();
    for (int s = 128; s > 0; s >>= 1) { if (tid < s) red[tid] += red[tid + s]; __syncthreads(); }
    float scale = rsqrtf(red[0] / (float)HHD + EPSV);
    float* out = o + (size_t)t * HHD;
    for (int j = tid; j < HHD; j += 256) out[j] = r[j] * scale * w[j];
}

// ---------------- rope + q/k rmsnorm ----------------
__global__ __launch_bounds__(256) void ropenorm_kernel(
    float* __restrict__ qkv, const int* __restrict__ pos,
    const float* __restrict__ qw, const float* __restrict__ kw)
{
    int t = blockIdx.x, tid = threadIdx.x;
    float* row = qkv + (size_t)t * QKVN;
    float p = (float)pos[t];
    const float lgt = logf(500000.0f);
    __shared__ float red[256];
    __shared__ float sq, sk;

    float ss = 0.f;
    for (int idx = tid; idx < 1024; idx += 256) {
        int hh = idx >> 6, i = idx & 63;
        float inv = expf(-lgt * (float)i * (1.0f / 64.0f));
        float fr = p * inv, c = cosf(fr), s = sinf(fr);
        float x1 = row[hh * 128 + i], x2 = row[hh * 128 + 64 + i];
        float o1 = x1 * c - x2 * s, o2 = x2 * c + x1 * s;
        row[hh * 128 + i] = o1; row[hh * 128 + 64 + i] = o2;
        ss += o1 * o1 + o2 * o2;
    }
    red[tid] = ss; __syncthreads();
    for (int s2 = 128; s2 > 0; s2 >>= 1) { if (tid < s2) red[tid] += red[tid + s2]; __syncthreads(); }
    if (tid == 0) sq = rsqrtf(red[0] / (float)QSZ + EPSV);
    __syncthreads();

    float ssk = 0.f;
    {
        int hh = tid >> 6, i = tid & 63;
        float inv = expf(-lgt * (float)i * (1.0f / 64.0f));
        float fr = p * inv, c = cosf(fr), s = sinf(fr);
        float* kb = row + QSZ;
        float x1 = kb[hh * 128 + i], x2 = kb[hh * 128 + 64 + i];
        float o1 = x1 * c - x2 * s, o2 = x2 * c + x1 * s;
        kb[hh * 128 + i] = o1; kb[hh * 128 + 64 + i] = o2;
        ssk = o1 * o1 + o2 * o2;
    }
    red[tid] = ssk; __syncthreads();
    for (int s2 = 128; s2 > 0; s2 >>= 1) { if (tid < s2) red[tid] += red[tid + s2]; __syncthreads(); }
    if (tid == 0) sk = rsqrtf(red[0] / (float)KVSZ + EPSV);
    __syncthreads();

    for (int j = tid; j < QSZ; j += 256) row[j] *= sq * qw[j];
    for (int j = tid; j < KVSZ; j += 256) row[QSZ + j] *= sk * kw[j];
}

// ---------------- flash attention (fp32) ----------------
#define QKSTR 132
#define SMEM_ATTN ((3 * 64 * QKSTR + 64 * 64) * 4)

__global__ __launch_bounds__(256) void attn_kernel(
    const float* __restrict__ qkv, float* __restrict__ O)
{
    extern __shared__ float sh[];
    float* Qs = sh;
    float* Ks = sh + 64 * QKSTR;
    float* Vs = sh + 2 * 64 * QKSTR;
    float* Ps = sh + 3 * 64 * QKSTR;

    int m0 = blockIdx.x * 64;
    int h  = blockIdx.y;
    int kvh = h >> 2;
    int tid = threadIdx.x, lane = tid & 31, w = tid >> 5;
    const float scl = 0.08838834764831845f;

    for (int i = tid; i < 2048; i += 256) {
        int r = i >> 5, c = (i & 31) << 2;
        *(float4*)&Qs[r * QKSTR + c] =
            *(const float4*)&qkv[(size_t)(m0 + r) * QKVN + h * HDIM + c];
    }

    float mrow[8], lrow[8], oacc[8][4];
#pragma unroll
    for (int r = 0; r < 8; r++) {
        mrow[r] = -1e30f; lrow[r] = 0.f;
        oacc[r][0] = oacc[r][1] = oacc[r][2] = oacc[r][3] = 0.f;
    }
    int d0 = lane << 2;

    for (int n0 = 0; n0 <= m0; n0 += 64) {
        __syncthreads();
        for (int i = tid; i < 2048; i += 256) {
            int r = i >> 5, c = (i & 31) << 2;
            *(float4*)&Ks[r * QKSTR + c] =
                *(const float4*)&qkv[(size_t)(n0 + r) * QKVN + QSZ + kvh * HDIM + c];
            *(float4*)&Vs[r * QKSTR + c] =
                *(const float4*)&qkv[(size_t)(n0 + r) * QKVN + QSZ + KVSZ + kvh * HDIM + c];
        }
        __syncthreads();

        float s0[8] = {0,0,0,0,0,0,0,0};
        float s1[8] = {0,0,0,0,0,0,0,0};
        for (int k = 0; k < 128; k++) {
            float k0 = Ks[lane * QKSTR + k];
            float k1 = Ks[(lane + 32) * QKSTR + k];
#pragma unroll
            for (int r = 0; r < 8; r++) {
                float q = Qs[(w * 8 + r) * QKSTR + k];
                s0[r] += q * k0; s1[r] += q * k1;
            }
        }
        bool diag = (n0 + 63 > m0);
#pragma unroll
        for (int r = 0; r < 8; r++) {
            int grow = m0 + w * 8 + r;
            float v0 = s0[r] * scl, v1 = s1[r] * scl;
            if (diag) {
                if (n0 + lane      > grow) v0 = -1e30f;
                if (n0 + lane + 32 > grow) v1 = -1e30f;
            }
            float tmax = fmaxf(v0, v1);
#pragma unroll
            for (int o = 16; o; o >>= 1) tmax = fmaxf(tmax, __shfl_xor_sync(~0u, tmax, o));
            float nm = fmaxf(mrow[r], tmax);
            float p0 = __expf(v0 - nm), p1 = __expf(v1 - nm);
            float corr = __expf(mrow[r] - nm);
            float psum = p0 + p1;
#pragma unroll
            for (int o = 16; o; o >>= 1) psum += __shfl_xor_sync(~0u, psum, o);
            lrow[r] = lrow[r] * corr + psum;
            mrow[r] = nm;
            oacc[r][0] *= corr; oacc[r][1] *= corr; oacc[r][2] *= corr; oacc[r][3] *= corr;
            Ps[(w * 8 + r) * 64 + lane]      = p0;
            Ps[(w * 8 + r) * 64 + lane + 32] = p1;
        }
        __syncwarp();
        for (int n = 0; n < 64; n++) {
            float4 v = *(float4*)&Vs[n * QKSTR + d0];
#pragma unroll
            for (int r = 0; r < 8; r++) {
                float p = Ps[(w * 8 + r) * 64 + n];
                oacc[r][0] += p * v.x; oacc[r][1] += p * v.y;
                oacc[r][2] += p * v.z; oacc[r][3] += p * v.w;
            }
        }
    }
#pragma unroll
    for (int r = 0; r < 8; r++) {
        float inv = 1.0f / lrow[r];
        float4 o = make_float4(oacc[r][0] * inv, oacc[r][1] * inv,
                               oacc[r][2] * inv, oacc[r][3] * inv);
        *(float4*)&O[(size_t)(m0 + w * 8 + r) * QSZ + h * HDIM + d0] = o;
    }
}

// ---------------- router / permutation ----------------
__global__ void zero_kernel()
{
    int i = threadIdx.x;
    if (i < NEXP) { g_cnt[i] = 0; g_cur[i] = 0; }
}

__global__ __launch_bounds__(256) void router_kernel(
    const float* __restrict__ y, const float* __restrict__ rw)
{
    int t = blockIdx.x, tid = threadIdx.x;
    const float* x = y + (size_t)t * HHD;
    float part[NEXP] = {};
    for (int k = tid; k < HHD; k += 256) {
        float xv = x[k];
        const float* r = rw + (size_t)k * NEXP;
#pragma unroll
        for (int e = 0; e < NEXP; e++) part[e] += xv * r[e];
    }
    __shared__ float red[256];
    __shared__ float logit[NEXP];
    for (int e = 0; e < NEXP; e++) {
        red[tid] = part[e]; __syncthreads();
        for (int s = 128; s > 0; s >>= 1) { if (tid < s) red[tid] += red[tid + s]; __syncthreads(); }
        if (tid == 0) logit[e] = red[0];
        __syncthreads();
    }
    if (tid == 0) {
        int am = 0; float mv = logit[0];
        for (int e = 1; e < NEXP; e++) if (logit[e] > mv) { mv = logit[e]; am = e; }
        g_expert[t] = am;
        g_gate[t]   = 1.0f / (1.0f + expf(-mv));
        atomicAdd(&g_cnt[am], 1);
    }
}

__global__ void scan_kernel()
{
    int s = 0;
    for (int e = 0; e < NEXP; e++) { g_off[e] = s; s += g_cnt[e]; }
}

__global__ void scatter_kernel()
{
    int t = blockIdx.x * 256 + threadIdx.x;
    if (t >= TT) return;
    int e = g_expert[t];
    int p = atomicAdd(&g_cur[e], 1);
    g_perm[g_off[e] + p] = t;
}

// ---------------- silu ----------------
__global__ __launch_bounds__(256) void silu_kernel(float* __restrict__ g, const float* __restrict__ u)
{
    int i = blockIdx.x * 256 + threadIdx.x;
    float x = g[i];
    g[i] = (x / (1.0f + __expf(-x))) * u[i];
}

// ---------------- launcher ----------------
extern "C" void kernel_launch(void* const* d_in, const int* in_sizes, int n_in,
                              void* d_out, int out_size)
{
    const int*   positions = (const int*)  d_in[0];
    const float* hidden    = (const float*)d_in[1];
    const float* ln1       = (const float*)d_in[2];
    const float* ln2       = (const float*)d_in[3];
    const float* w_qkv     = (const float*)d_in[4];
    const float* w_o       = (const float*)d_in[5];
    const float* qnw       = (const float*)d_in[6];
    const float* knw       = (const float*)d_in[7];
    const float* rw        = (const float*)d_in[8];
    const float* wsg       = (const float*)d_in[9];
    const float* wsu       = (const float*)d_in[10];
    const float* wsd       = (const float*)d_in[11];
    const float* weg       = (const float*)d_in[12];
    const float* weu       = (const float*)d_in[13];
    const float* wed       = (const float*)d_in[14];
    float* out = (float*)d_out;

    void* p;
    cudaGetSymbolAddress(&p, g_xn);  float* xn  = (float*)p;
    cudaGetSymbolAddress(&p, g_qkv); float* qkv = (float*)p;
    cudaGetSymbolAddress(&p, g_att); float* att = (float*)p;
    cudaGetSymbolAddress(&p, g_x2);  float* x2  = (float*)p;
    cudaGetSymbolAddress(&p, g_y);   float* y   = (float*)p;
    cudaGetSymbolAddress(&p, g_g);   float* gg  = (float*)p;
    cudaGetSymbolAddress(&p, g_u);   float* uu  = (float*)p;
    cudaGetSymbolAddress(&p, g_wqkvT);  float* wqkvT  = (float*)p;
    cudaGetSymbolAddress(&p, g_wqkvTl); float* wqkvTl = (float*)p;
    cudaGetSymbolAddress(&p, g_woT);    float* woT    = (float*)p;
    cudaGetSymbolAddress(&p, g_woTl);   float* woTl   = (float*)p;
    cudaGetSymbolAddress(&p, g_wsgT);   float* wsgT   = (float*)p;
    cudaGetSymbolAddress(&p, g_wsuT);   float* wsuT   = (float*)p;
    cudaGetSymbolAddress(&p, g_wsdT);   float* wsdT   = (float*)p;
    cudaGetSymbolAddress(&p, g_wegT);   float* wegT   = (float*)p;
    cudaGetSymbolAddress(&p, g_weuT);   float* weuT   = (float*)p;
    cudaGetSymbolAddress(&p, g_wedT);   float* wedT   = (float*)p;

    cudaFuncSetAttribute(attn_kernel, cudaFuncAttributeMaxDynamicSharedMemorySize, SMEM_ATTN);
    cudaFuncSetAttribute(gemm_mma<0, false>, cudaFuncAttributeMaxDynamicSharedMemorySize, 2 * 2 * ASZ * 4);
    cudaFuncSetAttribute(gemm_mma<1, false>, cudaFuncAttributeMaxDynamicSharedMemorySize, 2 * 2 * ASZ * 4);
    cudaFuncSetAttribute(gemm_mma<2, false>, cudaFuncAttributeMaxDynamicSharedMemorySize, 2 * 2 * ASZ * 4);
    cudaFuncSetAttribute(gemm_mma<0, true>,  cudaFuncAttributeMaxDynamicSharedMemorySize, 2 * 4 * ASZ * 4);
    const int SM_P = 2 * 2 * ASZ * 4;   // 73728
    const int SM_C = 2 * 4 * ASZ * 4;   // 147456

    // weight prep: (N,K) K-major, tf32-rounded; hi/lo split for qkv & o
    transpose_split<<<dim3(QKVN / 32, HHD / 32), 256>>>(w_qkv, wqkvT, wqkvTl, HHD, QKVN);
    transpose_split<<<dim3(HHD / 32, QSZ / 32), 256>>>(w_o, woT, woTl, QSZ, HHD);
    transpose_tf32<<<dim3(II / 32, HHD / 32), 256>>>(wsg, wsgT, HHD, II);
    transpose_tf32<<<dim3(II / 32, HHD / 32), 256>>>(wsu, wsuT, HHD, II);
    transpose_tf32<<<dim3(HHD / 32, II / 32), 256>>>(wsd, wsdT, II, HHD);
    transpose_tf32<<<dim3(II / 32, HHD / 32, NEXP), 256>>>(weg, wegT, HHD, II);
    transpose_tf32<<<dim3(II / 32, HHD / 32, NEXP), 256>>>(weu, weuT, HHD, II);
    transpose_tf32<<<dim3(HHD / 32, II / 32, NEXP), 256>>>(wed, wedT, II, HHD);

    // 1. x = rmsnorm(hidden, ln1)
    rmsnorm_kernel<<<TT, 256>>>(hidden, ln1, xn);
    // 2. qkv = x @ w_qkv   (compensated tf32 — feeds the router path)
    gemm_mma<0, true><<<dim3(QKVN / 128, TT / 128), 256, SM_C>>>(xn, wqkvT, wqkvTl, qkv, TT, QKVN, HHD, nullptr);
    // 3. rope + q/k norm
    ropenorm_kernel<<<TT, 256>>>(qkv, positions, qnw, knw);
    // 4. attention
    attn_kernel<<<dim3(TT / 64, NHEADS), 256, SMEM_ATTN>>>(qkv, att);
    // 5. x2 = hidden + attn @ w_o   (compensated)
    gemm_mma<0, true><<<dim3(HHD / 128, TT / 128), 256, SM_C>>>(att, woT, woTl, x2, TT, HHD, QSZ, hidden);
    // 6. y = rmsnorm(x2, ln2)
    rmsnorm_kernel<<<TT, 256>>>(x2, ln2, y);
    // 7. router (fp32)
    zero_kernel<<<1, 32>>>();
    router_kernel<<<TT, 256>>>(y, rw);
    scan_kernel<<<1, 1>>>();
    scatter_kernel<<<TT / 256, 256>>>();
    // 8. shared expert (plain tf32)
    gemm_mma<0, false><<<dim3(II / 128, TT / 128), 256, SM_P>>>(y, wsgT, nullptr, gg, TT, II, HHD, nullptr);
    gemm_mma<0, false><<<dim3(II / 128, TT / 128), 256, SM_P>>>(y, wsuT, nullptr, uu, TT, II, HHD, nullptr);
    silu_kernel<<<(TT * II) / 256, 256>>>(gg, uu);
    gemm_mma<0, false><<<dim3(HHD / 128, TT / 128), 256, SM_P>>>(gg, wsdT, nullptr, out, TT, HHD, II, x2);
    // 9. routed experts (plain tf32, grouped)
    gemm_mma<1, false><<<dim3(II / 128, TT / 128, NEXP), 256, SM_P>>>(y, wegT, nullptr, gg, TT, II, HHD, nullptr);
    gemm_mma<1, false><<<dim3(II / 128, TT / 128, NEXP), 256, SM_P>>>(y, weuT, nullptr, uu, TT, II, HHD, nullptr);
    silu_kernel<<<(TT * II) / 256, 256>>>(gg, uu);
    gemm_mma<2, false><<<dim3(HHD / 128, TT / 128, NEXP), 256, SM_P>>>(gg, wedT, nullptr, out, TT, HHD, II, nullptr);
}

// round 5
// speedup vs baseline: 2.1748x; 1.0768x over previous
#include <cuda_runtime.h>
#include <math.h>
#include <stdint.h>

#define TT     2048
#define HHD    2048
#define NHEADS 16
#define HDIM   128
#define QSZ    2048
#define KVSZ   512
#define QKVN   3072
#define NEXP   8
#define II     4096
#define EPSV   1e-5f

// ---------------- device scratch ----------------
__device__ __align__(256) float g_xn  [TT * HHD];
__device__ __align__(256) float g_qkv [TT * QKVN];
__device__ __align__(256) float g_att [TT * QSZ];
__device__ __align__(256) float g_x2  [TT * HHD];
__device__ __align__(256) float g_y   [TT * HHD];
__device__ __align__(256) float g_g   [TT * II];
__device__ __align__(256) float g_u   [TT * II];
__device__ int   g_expert[TT];
__device__ float g_gate  [TT];
__device__ int   g_cnt[NEXP];
__device__ int   g_off[NEXP];
__device__ int   g_cur[NEXP];
__device__ int   g_perm[TT];
__device__ __align__(256) float g_wqkvT [QKVN * HHD];
__device__ __align__(256) float g_wqkvTl[QKVN * HHD];
__device__ __align__(256) float g_woT   [HHD * QSZ];
__device__ __align__(256) float g_woTl  [HHD * QSZ];
__device__ __align__(256) float g_wsgT  [II * HHD];
__device__ __align__(256) float g_wsuT  [II * HHD];
__device__ __align__(256) float g_wsdT  [HHD * II];
__device__ __align__(256) float g_wegT  [NEXP * II * HHD];
__device__ __align__(256) float g_weuT  [NEXP * II * HHD];
__device__ __align__(256) float g_wedT  [NEXP * HHD * II];

// ---------------- helpers ----------------
__device__ __forceinline__ uint32_t smem_u32(const void* p) {
    uint32_t a;
    asm("{ .reg .u64 t; cvta.to.shared.u64 t, %1; cvt.u32.u64 %0, t; }" : "=r"(a) : "l"(p));
    return a;
}
__device__ __forceinline__ uint32_t f2tf32(float x) {
    uint32_t r;
    asm("cvt.rna.tf32.f32 %0, %1;" : "=r"(r) : "f"(x));
    return r;
}
__device__ __forceinline__ void cpa16(uint32_t dst, const float* src) {
    asm volatile("cp.async.cg.shared.global [%0], [%1], 16;" :: "r"(dst), "l"(src) : "memory");
}
#define CP_COMMIT() asm volatile("cp.async.commit_group;" ::: "memory")
#define CP_WAIT1()  asm volatile("cp.async.wait_group 1;" ::: "memory")
#define CP_WAIT0()  asm volatile("cp.async.wait_group 0;" ::: "memory")

#define MMA_TF32(d, a, b0, b1) \
  asm volatile("mma.sync.aligned.m16n8k8.row.col.f32.tf32.tf32.f32 " \
    "{%0,%1,%2,%3}, {%4,%5,%6,%7}, {%8,%9}, {%0,%1,%2,%3};" \
    : "+f"((d)[0]), "+f"((d)[1]), "+f"((d)[2]), "+f"((d)[3]) \
    : "r"((a)[0]), "r"((a)[1]), "r"((a)[2]), "r"((a)[3]), "r"(b0), "r"(b1))

// ---------------- fast 64x64 transpose, tf32 round ----------------
// out[c*R + r] = rna(in[r*C + c]);  grid (C/64, R/64, batch), 256 threads
__global__ __launch_bounds__(256) void transpose_tf32(
    const float* __restrict__ in, float* __restrict__ out, int R, int C)
{
    __shared__ float t[64 * 65];
    size_t off = (size_t)blockIdx.z * (size_t)R * C;
    in += off; out += off;
    int c0 = blockIdx.x * 64, r0 = blockIdx.y * 64;
#pragma unroll
    for (int it = 0; it < 4; it++) {
        int idx = threadIdx.x + 256 * it;
        int r = idx >> 4, cq = (idx & 15) << 2;
        float4 v = *(const float4*)&in[(size_t)(r0 + r) * C + c0 + cq];
        t[(cq + 0) * 65 + r] = v.x;
        t[(cq + 1) * 65 + r] = v.y;
        t[(cq + 2) * 65 + r] = v.z;
        t[(cq + 3) * 65 + r] = v.w;
    }
    __syncthreads();
#pragma unroll
    for (int it = 0; it < 4; it++) {
        int idx = threadIdx.x + 256 * it;
        int c = idx >> 4, q = (idx & 15) << 2;
        float4 v = make_float4(
            __uint_as_float(f2tf32(t[c * 65 + q + 0])),
            __uint_as_float(f2tf32(t[c * 65 + q + 1])),
            __uint_as_float(f2tf32(t[c * 65 + q + 2])),
            __uint_as_float(f2tf32(t[c * 65 + q + 3])));
        *(float4*)&out[(size_t)(c0 + c) * R + r0 + q] = v;
    }
}

// split version: hi = rna(x), lo = rna(x - hi)
__global__ __launch_bounds__(256) void transpose_split(
    const float* __restrict__ in, float* __restrict__ hi, float* __restrict__ lo,
    int R, int C)
{
    __shared__ float t[64 * 65];
    int c0 = blockIdx.x * 64, r0 = blockIdx.y * 64;
#pragma unroll
    for (int it = 0; it < 4; it++) {
        int idx = threadIdx.x + 256 * it;
        int r = idx >> 4, cq = (idx & 15) << 2;
        float4 v = *(const float4*)&in[(size_t)(r0 + r) * C + c0 + cq];
        t[(cq + 0) * 65 + r] = v.x;
        t[(cq + 1) * 65 + r] = v.y;
        t[(cq + 2) * 65 + r] = v.z;
        t[(cq + 3) * 65 + r] = v.w;
    }
    __syncthreads();
#pragma unroll
    for (int it = 0; it < 4; it++) {
        int idx = threadIdx.x + 256 * it;
        int c = idx >> 4, q = (idx & 15) << 2;
        float4 h, l;
        float x0 = t[c * 65 + q + 0], x1 = t[c * 65 + q + 1];
        float x2 = t[c * 65 + q + 2], x3 = t[c * 65 + q + 3];
        h.x = __uint_as_float(f2tf32(x0)); l.x = __uint_as_float(f2tf32(x0 - h.x));
        h.y = __uint_as_float(f2tf32(x1)); l.y = __uint_as_float(f2tf32(x1 - h.y));
        h.z = __uint_as_float(f2tf32(x2)); l.z = __uint_as_float(f2tf32(x2 - h.z));
        h.w = __uint_as_float(f2tf32(x3)); l.w = __uint_as_float(f2tf32(x3 - h.w));
        size_t o = (size_t)(c0 + c) * R + r0 + q;
        *(float4*)&hi[o] = h;
        *(float4*)&lo[o] = l;
    }
}

// ---------------- tensor-core GEMM (mma.sync tf32) — unchanged from R4 ----------------
#define ASZ 4608

template<int MODE, bool COMP>
__global__ void __launch_bounds__(256) gemm_mma(
    const float* __restrict__ A, const float* __restrict__ BH,
    const float* __restrict__ BL, float* __restrict__ C,
    int M, int N, int K, const float* __restrict__ Res)
{
    constexpr int STG = COMP ? 4 * ASZ : 2 * ASZ;
    int e = blockIdx.z;
    int cnt = M, base = 0;
    if (MODE) {
        cnt = g_cnt[e]; base = g_off[e];
        if ((int)blockIdx.y * 128 >= cnt) return;
        BH += (size_t)e * (size_t)N * K;
    }
    int bm = blockIdx.y * 128, bn = blockIdx.x * 128;
    int tid = threadIdx.x, lane = tid & 31, warp = tid >> 5;
    int wm = warp & 3, wn = warp >> 2;
    int g = lane >> 2, tig = lane & 3;

    extern __shared__ __align__(16) float smf[];
    uint32_t smb = smem_u32(smf);
    const uint32_t* SM = (const uint32_t*)smf;

    const float* aptr[4]; const float* bhp[4]; const float* blp[4];
    uint32_t offT[4];
#pragma unroll
    for (int i = 0; i < 4; i++) {
        int idx = tid + 256 * i;
        int r = idx >> 3, cc = idx & 7;
        int row;
        if (MODE == 1) { int rr = bm + r; if (rr >= cnt) rr = cnt - 1; row = g_perm[base + rr]; }
        else if (MODE == 2) { int rr = bm + r; if (rr >= cnt) rr = cnt - 1; row = base + rr; }
        else row = bm + r;
        aptr[i] = A + (size_t)row * K + cc * 4;
        bhp[i]  = BH + (size_t)(bn + r) * K + cc * 4;
        if (COMP) blp[i] = BL + (size_t)(bn + r) * K + cc * 4;
        offT[i] = (uint32_t)(r * 36 + cc * 4) * 4;
    }

    float4 areg[4];
#pragma unroll
    for (int i = 0; i < 4; i++) areg[i] = *(const float4*)(aptr[i]);
#pragma unroll
    for (int i = 0; i < 4; i++) {
        cpa16(smb + ASZ * 4 + offT[i], bhp[i]);
        if (COMP) cpa16(smb + 3 * ASZ * 4 + offT[i], blp[i]);
    }
    CP_COMMIT();
#pragma unroll
    for (int i = 0; i < 4; i++) {
        uint32_t h0 = f2tf32(areg[i].x), h1 = f2tf32(areg[i].y),
                 h2 = f2tf32(areg[i].z), h3 = f2tf32(areg[i].w);
        asm volatile("st.shared.v4.b32 [%0], {%1,%2,%3,%4};"
                     :: "r"(smb + offT[i]), "r"(h0), "r"(h1), "r"(h2), "r"(h3) : "memory");
        if (COMP) {
            uint32_t l0 = f2tf32(areg[i].x - __uint_as_float(h0));
            uint32_t l1 = f2tf32(areg[i].y - __uint_as_float(h1));
            uint32_t l2 = f2tf32(areg[i].z - __uint_as_float(h2));
            uint32_t l3 = f2tf32(areg[i].w - __uint_as_float(h3));
            asm volatile("st.shared.v4.b32 [%0], {%1,%2,%3,%4};"
                         :: "r"(smb + 2 * ASZ * 4 + offT[i]), "r"(l0), "r"(l1), "r"(l2), "r"(l3) : "memory");
        }
    }

    float acc[2][8][4];
#pragma unroll
    for (int mt = 0; mt < 2; mt++)
#pragma unroll
        for (int nt = 0; nt < 8; nt++)
#pragma unroll
            for (int q = 0; q < 4; q++) acc[mt][nt][q] = 0.f;

    const int abase = (wm * 32 + g) * 36 + tig;
    const int bbase = (wn * 64 + g) * 36 + tig;
    const int KC = K / 32;

    for (int c = 0; c < KC; c++) {
        int s = c & 1;
        bool more = (c + 1 < KC);
        if (more) {
            uint32_t nb = smb + (uint32_t)(s ^ 1) * STG * 4;
#pragma unroll
            for (int i = 0; i < 4; i++) areg[i] = *(const float4*)(aptr[i] + (c + 1) * 32);
#pragma unroll
            for (int i = 0; i < 4; i++) {
                cpa16(nb + ASZ * 4 + offT[i], bhp[i] + (c + 1) * 32);
                if (COMP) cpa16(nb + 3 * ASZ * 4 + offT[i], blp[i] + (c + 1) * 32);
            }
            CP_COMMIT();
            CP_WAIT1();
        } else {
            CP_WAIT0();
        }
        __syncthreads();

        const uint32_t* AH = SM + s * STG;
        const uint32_t* BHs = AH + ASZ;
        const uint32_t* AL = AH + 2 * ASZ;
        const uint32_t* BLs = AH + 3 * ASZ;

#pragma unroll
        for (int ks = 0; ks < 4; ks++) {
            uint32_t ah[2][4], al[2][4];
#pragma unroll
            for (int mt = 0; mt < 2; mt++) {
                int a0 = abase + mt * 16 * 36 + ks * 8;
                ah[mt][0] = AH[a0];           ah[mt][1] = AH[a0 + 8 * 36];
                ah[mt][2] = AH[a0 + 4];       ah[mt][3] = AH[a0 + 8 * 36 + 4];
                if (COMP) {
                    al[mt][0] = AL[a0];       al[mt][1] = AL[a0 + 8 * 36];
                    al[mt][2] = AL[a0 + 4];   al[mt][3] = AL[a0 + 8 * 36 + 4];
                }
            }
#pragma unroll
            for (int nt = 0; nt < 8; nt++) {
                int b0i = bbase + nt * 8 * 36 + ks * 8;
                uint32_t b0 = BHs[b0i], b1 = BHs[b0i + 4];
#pragma unroll
                for (int mt = 0; mt < 2; mt++)
                    MMA_TF32(acc[mt][nt], ah[mt], b0, b1);
                if (COMP) {
                    uint32_t bl0 = BLs[b0i], bl1 = BLs[b0i + 4];
#pragma unroll
                    for (int mt = 0; mt < 2; mt++) {
                        MMA_TF32(acc[mt][nt], al[mt], b0, b1);
                        MMA_TF32(acc[mt][nt], ah[mt], bl0, bl1);
                    }
                }
            }
        }
        __syncthreads();

        if (more) {
            uint32_t nb = smb + (uint32_t)(s ^ 1) * STG * 4;
#pragma unroll
            for (int i = 0; i < 4; i++) {
                uint32_t h0 = f2tf32(areg[i].x), h1 = f2tf32(areg[i].y),
                         h2 = f2tf32(areg[i].z), h3 = f2tf32(areg[i].w);
                asm volatile("st.shared.v4.b32 [%0], {%1,%2,%3,%4};"
                             :: "r"(nb + offT[i]), "r"(h0), "r"(h1), "r"(h2), "r"(h3) : "memory");
                if (COMP) {
                    uint32_t l0 = f2tf32(areg[i].x - __uint_as_float(h0));
                    uint32_t l1 = f2tf32(areg[i].y - __uint_as_float(h1));
                    uint32_t l2 = f2tf32(areg[i].z - __uint_as_float(h2));
                    uint32_t l3 = f2tf32(areg[i].w - __uint_as_float(h3));
                    asm volatile("st.shared.v4.b32 [%0], {%1,%2,%3,%4};"
                                 :: "r"(nb + 2 * ASZ * 4 + offT[i]), "r"(l0), "r"(l1), "r"(l2), "r"(l3) : "memory");
                }
            }
        }
    }

#pragma unroll
    for (int mt = 0; mt < 2; mt++) {
        int mloc0 = wm * 32 + mt * 16 + g;
#pragma unroll
        for (int nt = 0; nt < 8; nt++) {
            int col = bn + wn * 64 + nt * 8 + 2 * tig;
            float* d = acc[mt][nt];
            if (MODE == 0) {
                size_t i0 = (size_t)(bm + mloc0) * N + col;
                size_t i1 = (size_t)(bm + mloc0 + 8) * N + col;
                float2 v0 = make_float2(d[0], d[1]);
                float2 v1 = make_float2(d[2], d[3]);
                if (Res) {
                    float2 r0 = *(const float2*)&Res[i0];
                    float2 r1 = *(const float2*)&Res[i1];
                    v0.x += r0.x; v0.y += r0.y; v1.x += r1.x; v1.y += r1.y;
                }
                *(float2*)&C[i0] = v0;
                *(float2*)&C[i1] = v1;
            } else if (MODE == 1) {
                if (bm + mloc0 < cnt) {
                    size_t i0 = (size_t)(base + bm + mloc0) * N + col;
                    *(float2*)&C[i0] = make_float2(d[0], d[1]);
                }
                if (bm + mloc0 + 8 < cnt) {
                    size_t i1 = (size_t)(base + bm + mloc0 + 8) * N + col;
                    *(float2*)&C[i1] = make_float2(d[2], d[3]);
                }
            } else {
                if (bm + mloc0 < cnt) {
                    int tok = g_perm[base + bm + mloc0];
                    float gt = g_gate[tok];
                    size_t i0 = (size_t)tok * N + col;
                    float2 o = *(const float2*)&C[i0];
                    o.x += gt * d[0]; o.y += gt * d[1];
                    *(float2*)&C[i0] = o;
                }
                if (bm + mloc0 + 8 < cnt) {
                    int tok = g_perm[base + bm + mloc0 + 8];
                    float gt = g_gate[tok];
                    size_t i1 = (size_t)tok * N + col;
                    float2 o = *(const float2*)&C[i1];
                    o.x += gt * d[2]; o.y += gt * d[3];
                    *(float2*)&C[i1] = o;
                }
            }
        }
    }
}

// ---------------- rmsnorm ----------------
__global__ __launch_bounds__(256) void rmsnorm_kernel(
    const float* __restrict__ x, const float* __restrict__ w, float* __restrict__ o)
{
    int t = blockIdx.x, tid = threadIdx.x;
    const float* r = x + (size_t)t * HHD;
    float ss = 0.f;
    for (int j = tid; j < HHD; j += 256) { float v = r[j]; ss += v * v; }
    __shared__ float red[256];
    red[tid] = ss; __syncthreads();
    for (int s = 128; s > 0; s >>= 1) { if (tid < s) red[tid] += red[tid + s]; __syncthreads(); }
    float scale = rsqrtf(red[0] / (float)HHD + EPSV);
    float* out = o + (size_t)t * HHD;
    for (int j = tid; j < HHD; j += 256) out[j] = r[j] * scale * w[j];
}

// ---------------- rope + q/k rmsnorm ----------------
__global__ __launch_bounds__(256) void ropenorm_kernel(
    float* __restrict__ qkv, const int* __restrict__ pos,
    const float* __restrict__ qw, const float* __restrict__ kw)
{
    int t = blockIdx.x, tid = threadIdx.x;
    float* row = qkv + (size_t)t * QKVN;
    float p = (float)pos[t];
    const float lgt = logf(500000.0f);
    __shared__ float red[256];
    __shared__ float sq, sk;

    float ss = 0.f;
    for (int idx = tid; idx < 1024; idx += 256) {
        int hh = idx >> 6, i = idx & 63;
        float inv = expf(-lgt * (float)i * (1.0f / 64.0f));
        float fr = p * inv, c = cosf(fr), s = sinf(fr);
        float x1 = row[hh * 128 + i], x2 = row[hh * 128 + 64 + i];
        float o1 = x1 * c - x2 * s, o2 = x2 * c + x1 * s;
        row[hh * 128 + i] = o1; row[hh * 128 + 64 + i] = o2;
        ss += o1 * o1 + o2 * o2;
    }
    red[tid] = ss; __syncthreads();
    for (int s2 = 128; s2 > 0; s2 >>= 1) { if (tid < s2) red[tid] += red[tid + s2]; __syncthreads(); }
    if (tid == 0) sq = rsqrtf(red[0] / (float)QSZ + EPSV);
    __syncthreads();

    float ssk = 0.f;
    {
        int hh = tid >> 6, i = tid & 63;
        float inv = expf(-lgt * (float)i * (1.0f / 64.0f));
        float fr = p * inv, c = cosf(fr), s = sinf(fr);
        float* kb = row + QSZ;
        float x1 = kb[hh * 128 + i], x2 = kb[hh * 128 + 64 + i];
        float o1 = x1 * c - x2 * s, o2 = x2 * c + x1 * s;
        kb[hh * 128 + i] = o1; kb[hh * 128 + 64 + i] = o2;
        ssk = o1 * o1 + o2 * o2;
    }
    red[tid] = ssk; __syncthreads();
    for (int s2 = 128; s2 > 0; s2 >>= 1) { if (tid < s2) red[tid] += red[tid + s2]; __syncthreads(); }
    if (tid == 0) sk = rsqrtf(red[0] / (float)KVSZ + EPSV);
    __syncthreads();

    for (int j = tid; j < QSZ; j += 256) row[j] *= sq * qw[j];
    for (int j = tid; j < KVSZ; j += 256) row[QSZ + j] *= sk * kw[j];
}

// ---------------- flash attention (fp32, float4-vectorized) ----------------
#define QKSTR 132
#define PSTR  68
#define SMEM_ATTN ((3 * 64 * QKSTR + 64 * PSTR) * 4)

__global__ __launch_bounds__(256) void attn_kernel(
    const float* __restrict__ qkv, float* __restrict__ O)
{
    extern __shared__ float sh[];
    float* Qs = sh;
    float* Ks = sh + 64 * QKSTR;
    float* Vs = sh + 2 * 64 * QKSTR;
    float* Ps = sh + 3 * 64 * QKSTR;

    int m0 = ((int)gridDim.x - 1 - (int)blockIdx.x) * 64;   // heavy tiles first
    int h  = blockIdx.y;
    int kvh = h >> 2;
    int tid = threadIdx.x, lane = tid & 31, w = tid >> 5;
    const float scl = 0.08838834764831845f;

    for (int i = tid; i < 2048; i += 256) {
        int r = i >> 5, c = (i & 31) << 2;
        *(float4*)&Qs[r * QKSTR + c] =
            *(const float4*)&qkv[(size_t)(m0 + r) * QKVN + h * HDIM + c];
    }

    float mrow[8], lrow[8], oacc[8][4];
#pragma unroll
    for (int r = 0; r < 8; r++) {
        mrow[r] = -1e30f; lrow[r] = 0.f;
        oacc[r][0] = oacc[r][1] = oacc[r][2] = oacc[r][3] = 0.f;
    }
    int d0 = lane << 2;

    for (int n0 = 0; n0 <= m0; n0 += 64) {
        __syncthreads();
        for (int i = tid; i < 2048; i += 256) {
            int r = i >> 5, c = (i & 31) << 2;
            *(float4*)&Ks[r * QKSTR + c] =
                *(const float4*)&qkv[(size_t)(n0 + r) * QKVN + QSZ + kvh * HDIM + c];
            *(float4*)&Vs[r * QKSTR + c] =
                *(const float4*)&qkv[(size_t)(n0 + r) * QKVN + QSZ + KVSZ + kvh * HDIM + c];
        }
        __syncthreads();

        // S = Q Kᵀ, float4-blocked over k
        float s0[8] = {0,0,0,0,0,0,0,0};
        float s1[8] = {0,0,0,0,0,0,0,0};
#pragma unroll 4
        for (int k = 0; k < 128; k += 4) {
            float4 k0 = *(float4*)&Ks[lane * QKSTR + k];
            float4 k1 = *(float4*)&Ks[(lane + 32) * QKSTR + k];
#pragma unroll
            for (int r = 0; r < 8; r++) {
                float4 q = *(float4*)&Qs[(w * 8 + r) * QKSTR + k];
                s0[r] += q.x * k0.x + q.y * k0.y + q.z * k0.z + q.w * k0.w;
                s1[r] += q.x * k1.x + q.y * k1.y + q.z * k1.z + q.w * k1.w;
            }
        }
        bool diag = (n0 + 63 > m0);
#pragma unroll
        for (int r = 0; r < 8; r++) {
            int grow = m0 + w * 8 + r;
            float v0 = s0[r] * scl, v1 = s1[r] * scl;
            if (diag) {
                if (n0 + lane      > grow) v0 = -1e30f;
                if (n0 + lane + 32 > grow) v1 = -1e30f;
            }
            float tmax = fmaxf(v0, v1);
#pragma unroll
            for (int o = 16; o; o >>= 1) tmax = fmaxf(tmax, __shfl_xor_sync(~0u, tmax, o));
            float nm = fmaxf(mrow[r], tmax);
            float p0 = __expf(v0 - nm), p1 = __expf(v1 - nm);
            float corr = __expf(mrow[r] - nm);
            float psum = p0 + p1;
#pragma unroll
            for (int o = 16; o; o >>= 1) psum += __shfl_xor_sync(~0u, psum, o);
            lrow[r] = lrow[r] * corr + psum;
            mrow[r] = nm;
            oacc[r][0] *= corr; oacc[r][1] *= corr; oacc[r][2] *= corr; oacc[r][3] *= corr;
            Ps[(w * 8 + r) * PSTR + lane]      = p0;
            Ps[(w * 8 + r) * PSTR + lane + 32] = p1;
        }
        __syncwarp();
        // O += P V, float4-blocked over n
#pragma unroll 2
        for (int n = 0; n < 64; n += 4) {
            float4 v0 = *(float4*)&Vs[(n + 0) * QKSTR + d0];
            float4 v1 = *(float4*)&Vs[(n + 1) * QKSTR + d0];
            float4 v2 = *(float4*)&Vs[(n + 2) * QKSTR + d0];
            float4 v3 = *(float4*)&Vs[(n + 3) * QKSTR + d0];
#pragma unroll
            for (int r = 0; r < 8; r++) {
                float4 pv = *(float4*)&Ps[(w * 8 + r) * PSTR + n];
                oacc[r][0] += pv.x * v0.x + pv.y * v1.x + pv.z * v2.x + pv.w * v3.x;
                oacc[r][1] += pv.x * v0.y + pv.y * v1.y + pv.z * v2.y + pv.w * v3.y;
                oacc[r][2] += pv.x * v0.z + pv.y * v1.z + pv.z * v2.z + pv.w * v3.z;
                oacc[r][3] += pv.x * v0.w + pv.y * v1.w + pv.z * v2.w + pv.w * v3.w;
            }
        }
    }
#pragma unroll
    for (int r = 0; r < 8; r++) {
        float inv = 1.0f / lrow[r];
        float4 o = make_float4(oacc[r][0] * inv, oacc[r][1] * inv,
                               oacc[r][2] * inv, oacc[r][3] * inv);
        *(float4*)&O[(size_t)(m0 + w * 8 + r) * QSZ + h * HDIM + d0] = o;
    }
}

// ---------------- router / permutation ----------------
__global__ void zero_kernel()
{
    int i = threadIdx.x;
    if (i < NEXP) { g_cnt[i] = 0; g_cur[i] = 0; }
}

__global__ __launch_bounds__(256) void router_kernel(
    const float* __restrict__ y, const float* __restrict__ rw)
{
    int t = blockIdx.x, tid = threadIdx.x;
    const float* x = y + (size_t)t * HHD;
    float part[NEXP] = {};
    for (int k = tid; k < HHD; k += 256) {
        float xv = x[k];
        const float* r = rw + (size_t)k * NEXP;
#pragma unroll
        for (int e = 0; e < NEXP; e++) part[e] += xv * r[e];
    }
    __shared__ float red[256];
    __shared__ float logit[NEXP];
    for (int e = 0; e < NEXP; e++) {
        red[tid] = part[e]; __syncthreads();
        for (int s = 128; s > 0; s >>= 1) { if (tid < s) red[tid] += red[tid + s]; __syncthreads(); }
        if (tid == 0) logit[e] = red[0];
        __syncthreads();
    }
    if (tid == 0) {
        int am = 0; float mv = logit[0];
        for (int e = 1; e < NEXP; e++) if (logit[e] > mv) { mv = logit[e]; am = e; }
        g_expert[t] = am;
        g_gate[t]   = 1.0f / (1.0f + expf(-mv));
        atomicAdd(&g_cnt[am], 1);
    }
}

__global__ void scan_kernel()
{
    int s = 0;
    for (int e = 0; e < NEXP; e++) { g_off[e] = s; s += g_cnt[e]; }
}

__global__ void scatter_kernel()
{
    int t = blockIdx.x * 256 + threadIdx.x;
    if (t >= TT) return;
    int e = g_expert[t];
    int p = atomicAdd(&g_cur[e], 1);
    g_perm[g_off[e] + p] = t;
}

// ---------------- silu ----------------
__global__ __launch_bounds__(256) void silu_kernel(float* __restrict__ g, const float* __restrict__ u)
{
    int i = blockIdx.x * 256 + threadIdx.x;
    float x = g[i];
    g[i] = (x / (1.0f + __expf(-x))) * u[i];
}

// ---------------- launcher ----------------
extern "C" void kernel_launch(void* const* d_in, const int* in_sizes, int n_in,
                              void* d_out, int out_size)
{
    const int*   positions = (const int*)  d_in[0];
    const float* hidden    = (const float*)d_in[1];
    const float* ln1       = (const float*)d_in[2];
    const float* ln2       = (const float*)d_in[3];
    const float* w_qkv     = (const float*)d_in[4];
    const float* w_o       = (const float*)d_in[5];
    const float* qnw       = (const float*)d_in[6];
    const float* knw       = (const float*)d_in[7];
    const float* rw        = (const float*)d_in[8];
    const float* wsg       = (const float*)d_in[9];
    const float* wsu       = (const float*)d_in[10];
    const float* wsd       = (const float*)d_in[11];
    const float* weg       = (const float*)d_in[12];
    const float* weu       = (const float*)d_in[13];
    const float* wed       = (const float*)d_in[14];
    float* out = (float*)d_out;

    void* p;
    cudaGetSymbolAddress(&p, g_xn);  float* xn  = (float*)p;
    cudaGetSymbolAddress(&p, g_qkv); float* qkv = (float*)p;
    cudaGetSymbolAddress(&p, g_att); float* att = (float*)p;
    cudaGetSymbolAddress(&p, g_x2);  float* x2  = (float*)p;
    cudaGetSymbolAddress(&p, g_y);   float* y   = (float*)p;
    cudaGetSymbolAddress(&p, g_g);   float* gg  = (float*)p;
    cudaGetSymbolAddress(&p, g_u);   float* uu  = (float*)p;
    cudaGetSymbolAddress(&p, g_wqkvT);  float* wqkvT  = (float*)p;
    cudaGetSymbolAddress(&p, g_wqkvTl); float* wqkvTl = (float*)p;
    cudaGetSymbolAddress(&p, g_woT);    float* woT    = (float*)p;
    cudaGetSymbolAddress(&p, g_woTl);   float* woTl   = (float*)p;
    cudaGetSymbolAddress(&p, g_wsgT);   float* wsgT   = (float*)p;
    cudaGetSymbolAddress(&p, g_wsuT);   float* wsuT   = (float*)p;
    cudaGetSymbolAddress(&p, g_wsdT);   float* wsdT   = (float*)p;
    cudaGetSymbolAddress(&p, g_wegT);   float* wegT   = (float*)p;
    cudaGetSymbolAddress(&p, g_weuT);   float* weuT   = (float*)p;
    cudaGetSymbolAddress(&p, g_wedT);   float* wedT   = (float*)p;

    cudaFuncSetAttribute(attn_kernel, cudaFuncAttributeMaxDynamicSharedMemorySize, SMEM_ATTN);
    cudaFuncSetAttribute(gemm_mma<0, false>, cudaFuncAttributeMaxDynamicSharedMemorySize, 2 * 2 * ASZ * 4);
    cudaFuncSetAttribute(gemm_mma<1, false>, cudaFuncAttributeMaxDynamicSharedMemorySize, 2 * 2 * ASZ * 4);
    cudaFuncSetAttribute(gemm_mma<2, false>, cudaFuncAttributeMaxDynamicSharedMemorySize, 2 * 2 * ASZ * 4);
    cudaFuncSetAttribute(gemm_mma<0, true>,  cudaFuncAttributeMaxDynamicSharedMemorySize, 2 * 4 * ASZ * 4);
    const int SM_P = 2 * 2 * ASZ * 4;
    const int SM_C = 2 * 4 * ASZ * 4;

    // weight prep: (N,K) K-major, tf32-rounded; hi/lo split for qkv & o
    transpose_split<<<dim3(QKVN / 64, HHD / 64), 256>>>(w_qkv, wqkvT, wqkvTl, HHD, QKVN);
    transpose_split<<<dim3(HHD / 64, QSZ / 64), 256>>>(w_o, woT, woTl, QSZ, HHD);
    transpose_tf32<<<dim3(II / 64, HHD / 64), 256>>>(wsg, wsgT, HHD, II);
    transpose_tf32<<<dim3(II / 64, HHD / 64), 256>>>(wsu, wsuT, HHD, II);
    transpose_tf32<<<dim3(HHD / 64, II / 64), 256>>>(wsd, wsdT, II, HHD);
    transpose_tf32<<<dim3(II / 64, HHD / 64, NEXP), 256>>>(weg, wegT, HHD, II);
    transpose_tf32<<<dim3(II / 64, HHD / 64, NEXP), 256>>>(weu, weuT, HHD, II);
    transpose_tf32<<<dim3(HHD / 64, II / 64, NEXP), 256>>>(wed, wedT, II, HHD);

    // 1. x = rmsnorm(hidden, ln1)
    rmsnorm_kernel<<<TT, 256>>>(hidden, ln1, xn);
    // 2. qkv = x @ w_qkv   (compensated tf32 — upstream of router)
    gemm_mma<0, true><<<dim3(QKVN / 128, TT / 128), 256, SM_C>>>(xn, wqkvT, wqkvTl, qkv, TT, QKVN, HHD, nullptr);
    // 3. rope + q/k norm
    ropenorm_kernel<<<TT, 256>>>(qkv, positions, qnw, knw);
    // 4. attention (fp32, vectorized)
    attn_kernel<<<dim3(TT / 64, NHEADS), 256, SMEM_ATTN>>>(qkv, att);
    // 5. x2 = hidden + attn @ w_o   (compensated)
    gemm_mma<0, true><<<dim3(HHD / 128, TT / 128), 256, SM_C>>>(att, woT, woTl, x2, TT, HHD, QSZ, hidden);
    // 6. y = rmsnorm(x2, ln2)
    rmsnorm_kernel<<<TT, 256>>>(x2, ln2, y);
    // 7. router (fp32)
    zero_kernel<<<1, 32>>>();
    router_kernel<<<TT, 256>>>(y, rw);
    scan_kernel<<<1, 1>>>();
    scatter_kernel<<<TT / 256, 256>>>();
    // 8. shared expert (plain tf32)
    gemm_mma<0, false><<<dim3(II / 128, TT / 128), 256, SM_P>>>(y, wsgT, nullptr, gg, TT, II, HHD, nullptr);
    gemm_mma<0, false><<<dim3(II / 128, TT / 128), 256, SM_P>>>(y, wsuT, nullptr, uu, TT, II, HHD, nullptr);
    silu_kernel<<<(TT * II) / 256, 256>>>(gg, uu);
    gemm_mma<0, false><<<dim3(HHD / 128, TT / 128), 256, SM_P>>>(gg, wsdT, nullptr, out, TT, HHD, II, x2);
    // 9. routed experts (plain tf32, grouped)
    gemm_mma<1, false><<<dim3(II / 128, TT / 128, NEXP), 256, SM_P>>>(y, wegT, nullptr, gg, TT, II, HHD, nullptr);
    gemm_mma<1, false><<<dim3(II / 128, TT / 128, NEXP), 256, SM_P>>>(y, weuT, nullptr, uu, TT, II, HHD, nullptr);
    silu_kernel<<<(TT * II) / 256, 256>>>(gg, uu);
    gemm_mma<2, false><<<dim3(HHD / 128, TT / 128, NEXP), 256, SM_P>>>(gg, wedT, nullptr, out, TT, HHD, II, nullptr);
}

// round 6
// speedup vs baseline: 2.6681x; 1.2269x over previous
#include <cuda_runtime.h>
#include <cuda_fp16.h>
#include <math.h>
#include <stdint.h>

#define TT     2048
#define HHD    2048
#define NHEADS 16
#define HDIM   128
#define QSZ    2048
#define KVSZ   512
#define QKVN   3072
#define NEXP   8
#define II     4096
#define EPSV   1e-5f

// ---------------- device scratch ----------------
__device__ __align__(256) float g_xn  [TT * HHD];
__device__ __align__(256) float g_qkv [TT * QKVN];
__device__ __align__(256) float g_att [TT * QSZ];
__device__ __align__(256) float g_x2  [TT * HHD];
__device__ __align__(256) float g_y   [TT * HHD];
__device__ __align__(256) float g_g   [TT * II];
__device__ __align__(256) float g_u   [TT * II];
__device__ int   g_expert[TT];
__device__ float g_gate  [TT];
__device__ int   g_cnt[NEXP];
__device__ int   g_off[NEXP];
__device__ int   g_cur[NEXP];
__device__ int   g_perm[TT];
__device__ __align__(256) float g_wqkvT [QKVN * HHD];
__device__ __align__(256) float g_wqkvTl[QKVN * HHD];
__device__ __align__(256) float g_woT   [HHD * QSZ];
__device__ __align__(256) float g_woTl  [HHD * QSZ];
// fp16 weight buffers (reuse float-sized arrays, cast to __half*)
__device__ __align__(256) float g_wsgT  [II * HHD / 2];
__device__ __align__(256) float g_wsuT  [II * HHD / 2];
__device__ __align__(256) float g_wsdT  [HHD * II / 2];
__device__ __align__(256) float g_wegT  [NEXP * II * HHD / 2];
__device__ __align__(256) float g_weuT  [NEXP * II * HHD / 2];
__device__ __align__(256) float g_wedT  [NEXP * HHD * II / 2];

// ---------------- helpers ----------------
__device__ __forceinline__ uint32_t smem_u32(const void* p) {
    uint32_t a;
    asm("{ .reg .u64 t; cvta.to.shared.u64 t, %1; cvt.u32.u64 %0, t; }" : "=r"(a) : "l"(p));
    return a;
}
__device__ __forceinline__ uint32_t f2tf32(float x) {
    uint32_t r;
    asm("cvt.rna.tf32.f32 %0, %1;" : "=r"(r) : "f"(x));
    return r;
}
__device__ __forceinline__ uint32_t packh2(float a, float b) {
    __half2 h = __floats2half2_rn(a, b);
    return *(uint32_t*)&h;
}
__device__ __forceinline__ void cpa16(uint32_t dst, const void* src) {
    asm volatile("cp.async.cg.shared.global [%0], [%1], 16;" :: "r"(dst), "l"(src) : "memory");
}
#define CP_COMMIT() asm volatile("cp.async.commit_group;" ::: "memory")
#define CP_WAIT1()  asm volatile("cp.async.wait_group 1;" ::: "memory")
#define CP_WAIT0()  asm volatile("cp.async.wait_group 0;" ::: "memory")

#define MMA_TF32(d, a, b0, b1) \
  asm volatile("mma.sync.aligned.m16n8k8.row.col.f32.tf32.tf32.f32 " \
    "{%0,%1,%2,%3}, {%4,%5,%6,%7}, {%8,%9}, {%0,%1,%2,%3};" \
    : "+f"((d)[0]), "+f"((d)[1]), "+f"((d)[2]), "+f"((d)[3]) \
    : "r"((a)[0]), "r"((a)[1]), "r"((a)[2]), "r"((a)[3]), "r"(b0), "r"(b1))

#define MMA_F16(d, a, b0, b1) \
  asm volatile("mma.sync.aligned.m16n8k16.row.col.f32.f16.f16.f32 " \
    "{%0,%1,%2,%3}, {%4,%5,%6,%7}, {%8,%9}, {%0,%1,%2,%3};" \
    : "+f"((d)[0]), "+f"((d)[1]), "+f"((d)[2]), "+f"((d)[3]) \
    : "r"((a)[0]), "r"((a)[1]), "r"((a)[2]), "r"((a)[3]), "r"(b0), "r"(b1))

// ---------------- transposes ----------------
// split (tf32 hi/lo) for router-upstream weights
__global__ __launch_bounds__(256) void transpose_split(
    const float* __restrict__ in, float* __restrict__ hi, float* __restrict__ lo,
    int R, int C)
{
    __shared__ float t[64 * 65];
    int c0 = blockIdx.x * 64, r0 = blockIdx.y * 64;
#pragma unroll
    for (int it = 0; it < 4; it++) {
        int idx = threadIdx.x + 256 * it;
        int r = idx >> 4, cq = (idx & 15) << 2;
        float4 v = *(const float4*)&in[(size_t)(r0 + r) * C + c0 + cq];
        t[(cq + 0) * 65 + r] = v.x;
        t[(cq + 1) * 65 + r] = v.y;
        t[(cq + 2) * 65 + r] = v.z;
        t[(cq + 3) * 65 + r] = v.w;
    }
    __syncthreads();
#pragma unroll
    for (int it = 0; it < 4; it++) {
        int idx = threadIdx.x + 256 * it;
        int c = idx >> 4, q = (idx & 15) << 2;
        float4 h, l;
        float x0 = t[c * 65 + q + 0], x1 = t[c * 65 + q + 1];
        float x2 = t[c * 65 + q + 2], x3 = t[c * 65 + q + 3];
        h.x = __uint_as_float(f2tf32(x0)); l.x = __uint_as_float(f2tf32(x0 - h.x));
        h.y = __uint_as_float(f2tf32(x1)); l.y = __uint_as_float(f2tf32(x1 - h.y));
        h.z = __uint_as_float(f2tf32(x2)); l.z = __uint_as_float(f2tf32(x2 - h.z));
        h.w = __uint_as_float(f2tf32(x3)); l.w = __uint_as_float(f2tf32(x3 - h.w));
        size_t o = (size_t)(c0 + c) * R + r0 + q;
        *(float4*)&hi[o] = h;
        *(float4*)&lo[o] = l;
    }
}

// fp16 transpose for plain-path weights: out[c*R+r] = h(in[r*C+c])
__global__ __launch_bounds__(256) void transpose_f16(
    const float* __restrict__ in, __half* __restrict__ out, int R, int C)
{
    __shared__ float t[64 * 65];
    in  += (size_t)blockIdx.z * (size_t)R * C;
    out += (size_t)blockIdx.z * (size_t)R * C;
    int c0 = blockIdx.x * 64, r0 = blockIdx.y * 64;
#pragma unroll
    for (int it = 0; it < 4; it++) {
        int idx = threadIdx.x + 256 * it;
        int r = idx >> 4, cq = (idx & 15) << 2;
        float4 v = *(const float4*)&in[(size_t)(r0 + r) * C + c0 + cq];
        t[(cq + 0) * 65 + r] = v.x;
        t[(cq + 1) * 65 + r] = v.y;
        t[(cq + 2) * 65 + r] = v.z;
        t[(cq + 3) * 65 + r] = v.w;
    }
    __syncthreads();
#pragma unroll
    for (int it = 0; it < 4; it++) {
        int idx = threadIdx.x + 256 * it;
        int c = idx >> 4, q = (idx & 15) << 2;
        uint2 v;
        v.x = packh2(t[c * 65 + q + 0], t[c * 65 + q + 1]);
        v.y = packh2(t[c * 65 + q + 2], t[c * 65 + q + 3]);
        *(uint2*)&out[(size_t)(c0 + c) * R + r0 + q] = v;
    }
}

// ---------------- compensated tf32 GEMM (unchanged, COMP only) ----------------
#define ASZ 4608

template<int MODE, bool COMP>
__global__ void __launch_bounds__(256) gemm_mma(
    const float* __restrict__ A, const float* __restrict__ BH,
    const float* __restrict__ BL, float* __restrict__ C,
    int M, int N, int K, const float* __restrict__ Res)
{
    constexpr int STG = COMP ? 4 * ASZ : 2 * ASZ;
    int e = blockIdx.z;
    int cnt = M, base = 0;
    if (MODE) {
        cnt = g_cnt[e]; base = g_off[e];
        if ((int)blockIdx.y * 128 >= cnt) return;
        BH += (size_t)e * (size_t)N * K;
    }
    int bm = blockIdx.y * 128, bn = blockIdx.x * 128;
    int tid = threadIdx.x, lane = tid & 31, warp = tid >> 5;
    int wm = warp & 3, wn = warp >> 2;
    int g = lane >> 2, tig = lane & 3;

    extern __shared__ __align__(16) float smf[];
    uint32_t smb = smem_u32(smf);
    const uint32_t* SM = (const uint32_t*)smf;

    const float* aptr[4]; const float* bhp[4]; const float* blp[4];
    uint32_t offT[4];
#pragma unroll
    for (int i = 0; i < 4; i++) {
        int idx = tid + 256 * i;
        int r = idx >> 3, cc = idx & 7;
        int row;
        if (MODE == 1) { int rr = bm + r; if (rr >= cnt) rr = cnt - 1; row = g_perm[base + rr]; }
        else if (MODE == 2) { int rr = bm + r; if (rr >= cnt) rr = cnt - 1; row = base + rr; }
        else row = bm + r;
        aptr[i] = A + (size_t)row * K + cc * 4;
        bhp[i]  = BH + (size_t)(bn + r) * K + cc * 4;
        if (COMP) blp[i] = BL + (size_t)(bn + r) * K + cc * 4;
        offT[i] = (uint32_t)(r * 36 + cc * 4) * 4;
    }

    float4 areg[4];
#pragma unroll
    for (int i = 0; i < 4; i++) areg[i] = *(const float4*)(aptr[i]);
#pragma unroll
    for (int i = 0; i < 4; i++) {
        cpa16(smb + ASZ * 4 + offT[i], bhp[i]);
        if (COMP) cpa16(smb + 3 * ASZ * 4 + offT[i], blp[i]);
    }
    CP_COMMIT();
#pragma unroll
    for (int i = 0; i < 4; i++) {
        uint32_t h0 = f2tf32(areg[i].x), h1 = f2tf32(areg[i].y),
                 h2 = f2tf32(areg[i].z), h3 = f2tf32(areg[i].w);
        asm volatile("st.shared.v4.b32 [%0], {%1,%2,%3,%4};"
                     :: "r"(smb + offT[i]), "r"(h0), "r"(h1), "r"(h2), "r"(h3) : "memory");
        if (COMP) {
            uint32_t l0 = f2tf32(areg[i].x - __uint_as_float(h0));
            uint32_t l1 = f2tf32(areg[i].y - __uint_as_float(h1));
            uint32_t l2 = f2tf32(areg[i].z - __uint_as_float(h2));
            uint32_t l3 = f2tf32(areg[i].w - __uint_as_float(h3));
            asm volatile("st.shared.v4.b32 [%0], {%1,%2,%3,%4};"
                         :: "r"(smb + 2 * ASZ * 4 + offT[i]), "r"(l0), "r"(l1), "r"(l2), "r"(l3) : "memory");
        }
    }

    float acc[2][8][4];
#pragma unroll
    for (int mt = 0; mt < 2; mt++)
#pragma unroll
        for (int nt = 0; nt < 8; nt++)
#pragma unroll
            for (int q = 0; q < 4; q++) acc[mt][nt][q] = 0.f;

    const int abase = (wm * 32 + g) * 36 + tig;
    const int bbase = (wn * 64 + g) * 36 + tig;
    const int KC = K / 32;

    for (int c = 0; c < KC; c++) {
        int s = c & 1;
        bool more = (c + 1 < KC);
        if (more) {
            uint32_t nb = smb + (uint32_t)(s ^ 1) * STG * 4;
#pragma unroll
            for (int i = 0; i < 4; i++) areg[i] = *(const float4*)(aptr[i] + (c + 1) * 32);
#pragma unroll
            for (int i = 0; i < 4; i++) {
                cpa16(nb + ASZ * 4 + offT[i], bhp[i] + (c + 1) * 32);
                if (COMP) cpa16(nb + 3 * ASZ * 4 + offT[i], blp[i] + (c + 1) * 32);
            }
            CP_COMMIT();
            CP_WAIT1();
        } else {
            CP_WAIT0();
        }
        __syncthreads();

        const uint32_t* AH = SM + s * STG;
        const uint32_t* BHs = AH + ASZ;
        const uint32_t* AL = AH + 2 * ASZ;
        const uint32_t* BLs = AH + 3 * ASZ;

#pragma unroll
        for (int ks = 0; ks < 4; ks++) {
            uint32_t ah[2][4], al[2][4];
#pragma unroll
            for (int mt = 0; mt < 2; mt++) {
                int a0 = abase + mt * 16 * 36 + ks * 8;
                ah[mt][0] = AH[a0];           ah[mt][1] = AH[a0 + 8 * 36];
                ah[mt][2] = AH[a0 + 4];       ah[mt][3] = AH[a0 + 8 * 36 + 4];
                if (COMP) {
                    al[mt][0] = AL[a0];       al[mt][1] = AL[a0 + 8 * 36];
                    al[mt][2] = AL[a0 + 4];   al[mt][3] = AL[a0 + 8 * 36 + 4];
                }
            }
#pragma unroll
            for (int nt = 0; nt < 8; nt++) {
                int b0i = bbase + nt * 8 * 36 + ks * 8;
                uint32_t b0 = BHs[b0i], b1 = BHs[b0i + 4];
#pragma unroll
                for (int mt = 0; mt < 2; mt++)
                    MMA_TF32(acc[mt][nt], ah[mt], b0, b1);
                if (COMP) {
                    uint32_t bl0 = BLs[b0i], bl1 = BLs[b0i + 4];
#pragma unroll
                    for (int mt = 0; mt < 2; mt++) {
                        MMA_TF32(acc[mt][nt], al[mt], b0, b1);
                        MMA_TF32(acc[mt][nt], ah[mt], bl0, bl1);
                    }
                }
            }
        }
        __syncthreads();

        if (more) {
            uint32_t nb = smb + (uint32_t)(s ^ 1) * STG * 4;
#pragma unroll
            for (int i = 0; i < 4; i++) {
                uint32_t h0 = f2tf32(areg[i].x), h1 = f2tf32(areg[i].y),
                         h2 = f2tf32(areg[i].z), h3 = f2tf32(areg[i].w);
                asm volatile("st.shared.v4.b32 [%0], {%1,%2,%3,%4};"
                             :: "r"(nb + offT[i]), "r"(h0), "r"(h1), "r"(h2), "r"(h3) : "memory");
                if (COMP) {
                    uint32_t l0 = f2tf32(areg[i].x - __uint_as_float(h0));
                    uint32_t l1 = f2tf32(areg[i].y - __uint_as_float(h1));
                    uint32_t l2 = f2tf32(areg[i].z - __uint_as_float(h2));
                    uint32_t l3 = f2tf32(areg[i].w - __uint_as_float(h3));
                    asm volatile("st.shared.v4.b32 [%0], {%1,%2,%3,%4};"
                                 :: "r"(nb + 2 * ASZ * 4 + offT[i]), "r"(l0), "r"(l1), "r"(l2), "r"(l3) : "memory");
                }
            }
        }
    }

#pragma unroll
    for (int mt = 0; mt < 2; mt++) {
        int mloc0 = wm * 32 + mt * 16 + g;
#pragma unroll
        for (int nt = 0; nt < 8; nt++) {
            int col = bn + wn * 64 + nt * 8 + 2 * tig;
            float* d = acc[mt][nt];
            size_t i0 = (size_t)(bm + mloc0) * N + col;
            size_t i1 = (size_t)(bm + mloc0 + 8) * N + col;
            float2 v0 = make_float2(d[0], d[1]);
            float2 v1 = make_float2(d[2], d[3]);
            if (Res) {
                float2 r0 = *(const float2*)&Res[i0];
                float2 r1 = *(const float2*)&Res[i1];
                v0.x += r0.x; v0.y += r0.y; v1.x += r1.x; v1.y += r1.y;
            }
            *(float2*)&C[i0] = v0;
            *(float2*)&C[i1] = v1;
        }
    }
}

// ---------------- fp16 GEMM (plain paths): C = A@B, weights fp16 ----------------
// Tile 128x128x32; smem rows = 32 halves + 8 pad = 20 words.
#define HSTR 20
#define HTILE (128 * HSTR)       // words per tile
#define HSTG  (2 * HTILE)        // words per stage (A + B)
#define SMEM_H (2 * HSTG * 4)    // 40960 bytes

template<int MODE>
__global__ void __launch_bounds__(256) gemm_h(
    const float* __restrict__ A, const __half* __restrict__ BT,
    float* __restrict__ C, int M, int N, int K, const float* __restrict__ Res)
{
    int e = blockIdx.z;
    int cnt = M, base = 0;
    if (MODE) {
        cnt = g_cnt[e]; base = g_off[e];
        if ((int)blockIdx.y * 128 >= cnt) return;
        BT += (size_t)e * (size_t)N * K;
    }
    int bm = blockIdx.y * 128, bn = blockIdx.x * 128;
    int tid = threadIdx.x, lane = tid & 31, warp = tid >> 5;
    int wm = warp & 3, wn = warp >> 2;
    int g = lane >> 2, tig = lane & 3;

    extern __shared__ __align__(16) float smf[];
    uint32_t smb = smem_u32(smf);
    const uint32_t* SM = (const uint32_t*)smf;

    // loaders: 2 chunks/thread for A (8 floats -> 8 halves) and B (16B cp.async)
    const float* aptr[2]; const __half* bptr[2];
    uint32_t aoff[2], boff[2];
#pragma unroll
    for (int i = 0; i < 2; i++) {
        int idx = tid + 256 * i;
        int r = idx >> 2, cg = idx & 3;
        int row;
        if (MODE == 1) { int rr = bm + r; if (rr >= cnt) rr = cnt - 1; row = g_perm[base + rr]; }
        else if (MODE == 2) { int rr = bm + r; if (rr >= cnt) rr = cnt - 1; row = base + rr; }
        else row = bm + r;
        aptr[i] = A + (size_t)row * K + cg * 8;
        bptr[i] = BT + (size_t)(bn + r) * K + cg * 8;
        aoff[i] = (uint32_t)(r * HSTR + cg * 4) * 4;
        boff[i] = (uint32_t)(HTILE + r * HSTR + cg * 4) * 4;
    }

    float4 areg[2][2];
    // prologue: stage 0
#pragma unroll
    for (int i = 0; i < 2; i++) {
        areg[i][0] = *(const float4*)(aptr[i]);
        areg[i][1] = *(const float4*)(aptr[i] + 4);
        cpa16(smb + boff[i], bptr[i]);
    }
    CP_COMMIT();
#pragma unroll
    for (int i = 0; i < 2; i++) {
        uint32_t w0 = packh2(areg[i][0].x, areg[i][0].y);
        uint32_t w1 = packh2(areg[i][0].z, areg[i][0].w);
        uint32_t w2 = packh2(areg[i][1].x, areg[i][1].y);
        uint32_t w3 = packh2(areg[i][1].z, areg[i][1].w);
        asm volatile("st.shared.v4.b32 [%0], {%1,%2,%3,%4};"
                     :: "r"(smb + aoff[i]), "r"(w0), "r"(w1), "r"(w2), "r"(w3) : "memory");
    }

    float acc[2][8][4];
#pragma unroll
    for (int mt = 0; mt < 2; mt++)
#pragma unroll
        for (int nt = 0; nt < 8; nt++)
#pragma unroll
            for (int q = 0; q < 4; q++) acc[mt][nt][q] = 0.f;

    const int abase = (wm * 32 + g) * HSTR + tig;
    const int bbase = (wn * 64 + g) * HSTR + tig;
    const int KC = K / 32;

    for (int c = 0; c < KC; c++) {
        int s = c & 1;
        bool more = (c + 1 < KC);
        if (more) {
            uint32_t nb = smb + (uint32_t)(s ^ 1) * HSTG * 4;
#pragma unroll
            for (int i = 0; i < 2; i++) {
                areg[i][0] = *(const float4*)(aptr[i] + (c + 1) * 32);
                areg[i][1] = *(const float4*)(aptr[i] + (c + 1) * 32 + 4);
                cpa16(nb + boff[i], bptr[i] + (c + 1) * 32);
            }
            CP_COMMIT();
            CP_WAIT1();
        } else {
            CP_WAIT0();
        }
        __syncthreads();

        const uint32_t* AH = SM + s * HSTG;
        const uint32_t* BH = AH + HTILE;

#pragma unroll
        for (int ks = 0; ks < 2; ks++) {
            uint32_t ah[2][4];
#pragma unroll
            for (int mt = 0; mt < 2; mt++) {
                int a0 = abase + mt * 16 * HSTR + ks * 8;
                ah[mt][0] = AH[a0];
                ah[mt][1] = AH[a0 + 8 * HSTR];
                ah[mt][2] = AH[a0 + 4];
                ah[mt][3] = AH[a0 + 8 * HSTR + 4];
            }
#pragma unroll
            for (int nt = 0; nt < 8; nt++) {
                int b0i = bbase + nt * 8 * HSTR + ks * 8;
                uint32_t b0 = BH[b0i], b1 = BH[b0i + 4];
#pragma unroll
                for (int mt = 0; mt < 2; mt++)
                    MMA_F16(acc[mt][nt], ah[mt], b0, b1);
            }
        }
        __syncthreads();

        if (more) {
            uint32_t nb = smb + (uint32_t)(s ^ 1) * HSTG * 4;
#pragma unroll
            for (int i = 0; i < 2; i++) {
                uint32_t w0 = packh2(areg[i][0].x, areg[i][0].y);
                uint32_t w1 = packh2(areg[i][0].z, areg[i][0].w);
                uint32_t w2 = packh2(areg[i][1].x, areg[i][1].y);
                uint32_t w3 = packh2(areg[i][1].z, areg[i][1].w);
                asm volatile("st.shared.v4.b32 [%0], {%1,%2,%3,%4};"
                             :: "r"(nb + aoff[i]), "r"(w0), "r"(w1), "r"(w2), "r"(w3) : "memory");
            }
        }
    }

    // epilogue
#pragma unroll
    for (int mt = 0; mt < 2; mt++) {
        int mloc0 = wm * 32 + mt * 16 + g;
#pragma unroll
        for (int nt = 0; nt < 8; nt++) {
            int col = bn + wn * 64 + nt * 8 + 2 * tig;
            float* d = acc[mt][nt];
            if (MODE == 0) {
                size_t i0 = (size_t)(bm + mloc0) * N + col;
                size_t i1 = (size_t)(bm + mloc0 + 8) * N + col;
                float2 v0 = make_float2(d[0], d[1]);
                float2 v1 = make_float2(d[2], d[3]);
                if (Res) {
                    float2 r0 = *(const float2*)&Res[i0];
                    float2 r1 = *(const float2*)&Res[i1];
                    v0.x += r0.x; v0.y += r0.y; v1.x += r1.x; v1.y += r1.y;
                }
                *(float2*)&C[i0] = v0;
                *(float2*)&C[i1] = v1;
            } else if (MODE == 1) {
                if (bm + mloc0 < cnt) {
                    size_t i0 = (size_t)(base + bm + mloc0) * N + col;
                    *(float2*)&C[i0] = make_float2(d[0], d[1]);
                }
                if (bm + mloc0 + 8 < cnt) {
                    size_t i1 = (size_t)(base + bm + mloc0 + 8) * N + col;
                    *(float2*)&C[i1] = make_float2(d[2], d[3]);
                }
            } else {
                if (bm + mloc0 < cnt) {
                    int tok = g_perm[base + bm + mloc0];
                    float gt = g_gate[tok];
                    size_t i0 = (size_t)tok * N + col;
                    float2 o = *(const float2*)&C[i0];
                    o.x += gt * d[0]; o.y += gt * d[1];
                    *(float2*)&C[i0] = o;
                }
                if (bm + mloc0 + 8 < cnt) {
                    int tok = g_perm[base + bm + mloc0 + 8];
                    float gt = g_gate[tok];
                    size_t i1 = (size_t)tok * N + col;
                    float2 o = *(const float2*)&C[i1];
                    o.x += gt * d[2]; o.y += gt * d[3];
                    *(float2*)&C[i1] = o;
                }
            }
        }
    }
}

// ---------------- rmsnorm ----------------
__global__ __launch_bounds__(256) void rmsnorm_kernel(
    const float* __restrict__ x, const float* __restrict__ w, float* __restrict__ o)
{
    int t = blockIdx.x, tid = threadIdx.x;
    const float* r = x + (size_t)t * HHD;
    float ss = 0.f;
    for (int j = tid; j < HHD; j += 256) { float v = r[j]; ss += v * v; }
    __shared__ float red[256];
    red[tid] = ss; __syncthreads();
    for (int s = 128; s > 0; s >>= 1) { if (tid < s) red[tid] += red[tid + s]; __syncthreads(); }
    float scale = rsqrtf(red[0] / (float)HHD + EPSV);
    float* out = o + (size_t)t * HHD;
    for (int j = tid; j < HHD; j += 256) out[j] = r[j] * scale * w[j];
}

// ---------------- rope + q/k rmsnorm ----------------
__global__ __launch_bounds__(256) void ropenorm_kernel(
    float* __restrict__ qkv, const int* __restrict__ pos,
    const float* __restrict__ qw, const float* __restrict__ kw)
{
    int t = blockIdx.x, tid = threadIdx.x;
    float* row = qkv + (size_t)t * QKVN;
    float p = (float)pos[t];
    const float lgt = logf(500000.0f);
    __shared__ float red[256];
    __shared__ float sq, sk;

    float ss = 0.f;
    for (int idx = tid; idx < 1024; idx += 256) {
        int hh = idx >> 6, i = idx & 63;
        float inv = expf(-lgt * (float)i * (1.0f / 64.0f));
        float fr = p * inv, c = cosf(fr), s = sinf(fr);
        float x1 = row[hh * 128 + i], x2 = row[hh * 128 + 64 + i];
        float o1 = x1 * c - x2 * s, o2 = x2 * c + x1 * s;
        row[hh * 128 + i] = o1; row[hh * 128 + 64 + i] = o2;
        ss += o1 * o1 + o2 * o2;
    }
    red[tid] = ss; __syncthreads();
    for (int s2 = 128; s2 > 0; s2 >>= 1) { if (tid < s2) red[tid] += red[tid + s2]; __syncthreads(); }
    if (tid == 0) sq = rsqrtf(red[0] / (float)QSZ + EPSV);
    __syncthreads();

    float ssk = 0.f;
    {
        int hh = tid >> 6, i = tid & 63;
        float inv = expf(-lgt * (float)i * (1.0f / 64.0f));
        float fr = p * inv, c = cosf(fr), s = sinf(fr);
        float* kb = row + QSZ;
        float x1 = kb[hh * 128 + i], x2 = kb[hh * 128 + 64 + i];
        float o1 = x1 * c - x2 * s, o2 = x2 * c + x1 * s;
        kb[hh * 128 + i] = o1; kb[hh * 128 + 64 + i] = o2;
        ssk = o1 * o1 + o2 * o2;
    }
    red[tid] = ssk; __syncthreads();
    for (int s2 = 128; s2 > 0; s2 >>= 1) { if (tid < s2) red[tid] += red[tid + s2]; __syncthreads(); }
    if (tid == 0) sk = rsqrtf(red[0] / (float)KVSZ + EPSV);
    __syncthreads();

    for (int j = tid; j < QSZ; j += 256) row[j] *= sq * qw[j];
    for (int j = tid; j < KVSZ; j += 256) row[QSZ + j] *= sk * kw[j];
}

// ---------------- flash attention (fp32, float4-vectorized) ----------------
#define QKSTR 132
#define PSTR  68
#define SMEM_ATTN ((3 * 64 * QKSTR + 64 * PSTR) * 4)

__global__ __launch_bounds__(256) void attn_kernel(
    const float* __restrict__ qkv, float* __restrict__ O)
{
    extern __shared__ float sh[];
    float* Qs = sh;
    float* Ks = sh + 64 * QKSTR;
    float* Vs = sh + 2 * 64 * QKSTR;
    float* Ps = sh + 3 * 64 * QKSTR;

    int m0 = ((int)gridDim.x - 1 - (int)blockIdx.x) * 64;
    int h  = blockIdx.y;
    int kvh = h >> 2;
    int tid = threadIdx.x, lane = tid & 31, w = tid >> 5;
    const float scl = 0.08838834764831845f;

    for (int i = tid; i < 2048; i += 256) {
        int r = i >> 5, c = (i & 31) << 2;
        *(float4*)&Qs[r * QKSTR + c] =
            *(const float4*)&qkv[(size_t)(m0 + r) * QKVN + h * HDIM + c];
    }

    float mrow[8], lrow[8], oacc[8][4];
#pragma unroll
    for (int r = 0; r < 8; r++) {
        mrow[r] = -1e30f; lrow[r] = 0.f;
        oacc[r][0] = oacc[r][1] = oacc[r][2] = oacc[r][3] = 0.f;
    }
    int d0 = lane << 2;

    for (int n0 = 0; n0 <= m0; n0 += 64) {
        __syncthreads();
        for (int i = tid; i < 2048; i += 256) {
            int r = i >> 5, c = (i & 31) << 2;
            *(float4*)&Ks[r * QKSTR + c] =
                *(const float4*)&qkv[(size_t)(n0 + r) * QKVN + QSZ + kvh * HDIM + c];
            *(float4*)&Vs[r * QKSTR + c] =
                *(const float4*)&qkv[(size_t)(n0 + r) * QKVN + QSZ + KVSZ + kvh * HDIM + c];
        }
        __syncthreads();

        float s0[8] = {0,0,0,0,0,0,0,0};
        float s1[8] = {0,0,0,0,0,0,0,0};
#pragma unroll 4
        for (int k = 0; k < 128; k += 4) {
            float4 k0 = *(float4*)&Ks[lane * QKSTR + k];
            float4 k1 = *(float4*)&Ks[(lane + 32) * QKSTR + k];
#pragma unroll
            for (int r = 0; r < 8; r++) {
                float4 q = *(float4*)&Qs[(w * 8 + r) * QKSTR + k];
                s0[r] += q.x * k0.x + q.y * k0.y + q.z * k0.z + q.w * k0.w;
                s1[r] += q.x * k1.x + q.y * k1.y + q.z * k1.z + q.w * k1.w;
            }
        }
        bool diag = (n0 + 63 > m0);
#pragma unroll
        for (int r = 0; r < 8; r++) {
            int grow = m0 + w * 8 + r;
            float v0 = s0[r] * scl, v1 = s1[r] * scl;
            if (diag) {
                if (n0 + lane      > grow) v0 = -1e30f;
                if (n0 + lane + 32 > grow) v1 = -1e30f;
            }
            float tmax = fmaxf(v0, v1);
#pragma unroll
            for (int o = 16; o; o >>= 1) tmax = fmaxf(tmax, __shfl_xor_sync(~0u, tmax, o));
            float nm = fmaxf(mrow[r], tmax);
            float p0 = __expf(v0 - nm), p1 = __expf(v1 - nm);
            float corr = __expf(mrow[r] - nm);
            float psum = p0 + p1;
#pragma unroll
            for (int o = 16; o; o >>= 1) psum += __shfl_xor_sync(~0u, psum, o);
            lrow[r] = lrow[r] * corr + psum;
            mrow[r] = nm;
            oacc[r][0] *= corr; oacc[r][1] *= corr; oacc[r][2] *= corr; oacc[r][3] *= corr;
            Ps[(w * 8 + r) * PSTR + lane]      = p0;
            Ps[(w * 8 + r) * PSTR + lane + 32] = p1;
        }
        __syncwarp();
#pragma unroll 2
        for (int n = 0; n < 64; n += 4) {
            float4 v0 = *(float4*)&Vs[(n + 0) * QKSTR + d0];
            float4 v1 = *(float4*)&Vs[(n + 1) * QKSTR + d0];
            float4 v2 = *(float4*)&Vs[(n + 2) * QKSTR + d0];
            float4 v3 = *(float4*)&Vs[(n + 3) * QKSTR + d0];
#pragma unroll
            for (int r = 0; r < 8; r++) {
                float4 pv = *(float4*)&Ps[(w * 8 + r) * PSTR + n];
                oacc[r][0] += pv.x * v0.x + pv.y * v1.x + pv.z * v2.x + pv.w * v3.x;
                oacc[r][1] += pv.x * v0.y + pv.y * v1.y + pv.z * v2.y + pv.w * v3.y;
                oacc[r][2] += pv.x * v0.z + pv.y * v1.z + pv.z * v2.z + pv.w * v3.z;
                oacc[r][3] += pv.x * v0.w + pv.y * v1.w + pv.z * v2.w + pv.w * v3.w;
            }
        }
    }
#pragma unroll
    for (int r = 0; r < 8; r++) {
        float inv = 1.0f / lrow[r];
        float4 o = make_float4(oacc[r][0] * inv, oacc[r][1] * inv,
                               oacc[r][2] * inv, oacc[r][3] * inv);
        *(float4*)&O[(size_t)(m0 + w * 8 + r) * QSZ + h * HDIM + d0] = o;
    }
}

// ---------------- router / permutation ----------------
__global__ void zero_kernel()
{
    int i = threadIdx.x;
    if (i < NEXP) { g_cnt[i] = 0; g_cur[i] = 0; }
}

__global__ __launch_bounds__(256) void router_kernel(
    const float* __restrict__ y, const float* __restrict__ rw)
{
    int t = blockIdx.x, tid = threadIdx.x;
    const float* x = y + (size_t)t * HHD;
    float part[NEXP] = {};
    for (int k = tid; k < HHD; k += 256) {
        float xv = x[k];
        const float* r = rw + (size_t)k * NEXP;
#pragma unroll
        for (int e = 0; e < NEXP; e++) part[e] += xv * r[e];
    }
    __shared__ float red[256];
    __shared__ float logit[NEXP];
    for (int e = 0; e < NEXP; e++) {
        red[tid] = part[e]; __syncthreads();
        for (int s = 128; s > 0; s >>= 1) { if (tid < s) red[tid] += red[tid + s]; __syncthreads(); }
        if (tid == 0) logit[e] = red[0];
        __syncthreads();
    }
    if (tid == 0) {
        int am = 0; float mv = logit[0];
        for (int e = 1; e < NEXP; e++) if (logit[e] > mv) { mv = logit[e]; am = e; }
        g_expert[t] = am;
        g_gate[t]   = 1.0f / (1.0f + expf(-mv));
        atomicAdd(&g_cnt[am], 1);
    }
}

__global__ void scan_kernel()
{
    int s = 0;
    for (int e = 0; e < NEXP; e++) { g_off[e] = s; s += g_cnt[e]; }
}

__global__ void scatter_kernel()
{
    int t = blockIdx.x * 256 + threadIdx.x;
    if (t >= TT) return;
    int e = g_expert[t];
    int p = atomicAdd(&g_cur[e], 1);
    g_perm[g_off[e] + p] = t;
}

// ---------------- silu ----------------
__global__ __launch_bounds__(256) void silu_kernel(float* __restrict__ g, const float* __restrict__ u)
{
    int i = blockIdx.x * 256 + threadIdx.x;
    float x = g[i];
    g[i] = (x / (1.0f + __expf(-x))) * u[i];
}

// ---------------- launcher ----------------
extern "C" void kernel_launch(void* const* d_in, const int* in_sizes, int n_in,
                              void* d_out, int out_size)
{
    const int*   positions = (const int*)  d_in[0];
    const float* hidden    = (const float*)d_in[1];
    const float* ln1       = (const float*)d_in[2];
    const float* ln2       = (const float*)d_in[3];
    const float* w_qkv     = (const float*)d_in[4];
    const float* w_o       = (const float*)d_in[5];
    const float* qnw       = (const float*)d_in[6];
    const float* knw       = (const float*)d_in[7];
    const float* rw        = (const float*)d_in[8];
    const float* wsg       = (const float*)d_in[9];
    const float* wsu       = (const float*)d_in[10];
    const float* wsd       = (const float*)d_in[11];
    const float* weg       = (const float*)d_in[12];
    const float* weu       = (const float*)d_in[13];
    const float* wed       = (const float*)d_in[14];
    float* out = (float*)d_out;

    void* p;
    cudaGetSymbolAddress(&p, g_xn);  float* xn  = (float*)p;
    cudaGetSymbolAddress(&p, g_qkv); float* qkv = (float*)p;
    cudaGetSymbolAddress(&p, g_att); float* att = (float*)p;
    cudaGetSymbolAddress(&p, g_x2);  float* x2  = (float*)p;
    cudaGetSymbolAddress(&p, g_y);   float* y   = (float*)p;
    cudaGetSymbolAddress(&p, g_g);   float* gg  = (float*)p;
    cudaGetSymbolAddress(&p, g_u);   float* uu  = (float*)p;
    cudaGetSymbolAddress(&p, g_wqkvT);  float* wqkvT  = (float*)p;
    cudaGetSymbolAddress(&p, g_wqkvTl); float* wqkvTl = (float*)p;
    cudaGetSymbolAddress(&p, g_woT);    float* woT    = (float*)p;
    cudaGetSymbolAddress(&p, g_woTl);   float* woTl   = (float*)p;
    cudaGetSymbolAddress(&p, g_wsgT);   __half* wsgT  = (__half*)p;
    cudaGetSymbolAddress(&p, g_wsuT);   __half* wsuT  = (__half*)p;
    cudaGetSymbolAddress(&p, g_wsdT);   __half* wsdT  = (__half*)p;
    cudaGetSymbolAddress(&p, g_wegT);   __half* wegT  = (__half*)p;
    cudaGetSymbolAddress(&p, g_weuT);   __half* weuT  = (__half*)p;
    cudaGetSymbolAddress(&p, g_wedT);   __half* wedT  = (__half*)p;

    cudaFuncSetAttribute(attn_kernel, cudaFuncAttributeMaxDynamicSharedMemorySize, SMEM_ATTN);
    cudaFuncSetAttribute(gemm_mma<0, true>, cudaFuncAttributeMaxDynamicSharedMemorySize, 2 * 4 * ASZ * 4);
    cudaFuncSetAttribute(gemm_h<0>, cudaFuncAttributeMaxDynamicSharedMemorySize, SMEM_H);
    cudaFuncSetAttribute(gemm_h<1>, cudaFuncAttributeMaxDynamicSharedMemorySize, SMEM_H);
    cudaFuncSetAttribute(gemm_h<2>, cudaFuncAttributeMaxDynamicSharedMemorySize, SMEM_H);
    const int SM_C = 2 * 4 * ASZ * 4;

    // weight prep
    transpose_split<<<dim3(QKVN / 64, HHD / 64), 256>>>(w_qkv, wqkvT, wqkvTl, HHD, QKVN);
    transpose_split<<<dim3(HHD / 64, QSZ / 64), 256>>>(w_o, woT, woTl, QSZ, HHD);
    transpose_f16<<<dim3(II / 64, HHD / 64), 256>>>(wsg, wsgT, HHD, II);
    transpose_f16<<<dim3(II / 64, HHD / 64), 256>>>(wsu, wsuT, HHD, II);
    transpose_f16<<<dim3(HHD / 64, II / 64), 256>>>(wsd, wsdT, II, HHD);
    transpose_f16<<<dim3(II / 64, HHD / 64, NEXP), 256>>>(weg, wegT, HHD, II);
    transpose_f16<<<dim3(II / 64, HHD / 64, NEXP), 256>>>(weu, weuT, HHD, II);
    transpose_f16<<<dim3(HHD / 64, II / 64, NEXP), 256>>>(wed, wedT, II, HHD);

    // 1. x = rmsnorm(hidden, ln1)
    rmsnorm_kernel<<<TT, 256>>>(hidden, ln1, xn);
    // 2. qkv = x @ w_qkv   (compensated tf32 — upstream of router)
    gemm_mma<0, true><<<dim3(QKVN / 128, TT / 128), 256, SM_C>>>(xn, wqkvT, wqkvTl, qkv, TT, QKVN, HHD, nullptr);
    // 3. rope + q/k norm
    ropenorm_kernel<<<TT, 256>>>(qkv, positions, qnw, knw);
    // 4. attention
    attn_kernel<<<dim3(TT / 64, NHEADS), 256, SMEM_ATTN>>>(qkv, att);
    // 5. x2 = hidden + attn @ w_o   (compensated)
    gemm_mma<0, true><<<dim3(HHD / 128, TT / 128), 256, SM_C>>>(att, woT, woTl, x2, TT, HHD, QSZ, hidden);
    // 6. y = rmsnorm(x2, ln2)
    rmsnorm_kernel<<<TT, 256>>>(x2, ln2, y);
    // 7. router (fp32)
    zero_kernel<<<1, 32>>>();
    router_kernel<<<TT, 256>>>(y, rw);
    scan_kernel<<<1, 1>>>();
    scatter_kernel<<<TT / 256, 256>>>();
    // 8. shared expert (fp16)
    gemm_h<0><<<dim3(II / 128, TT / 128), 256, SMEM_H>>>(y, wsgT, gg, TT, II, HHD, nullptr);
    gemm_h<0><<<dim3(II / 128, TT / 128), 256, SMEM_H>>>(y, wsuT, uu, TT, II, HHD, nullptr);
    silu_kernel<<<(TT * II) / 256, 256>>>(gg, uu);
    gemm_h<0><<<dim3(HHD / 128, TT / 128), 256, SMEM_H>>>(gg, wsdT, out, TT, HHD, II, x2);
    // 9. routed experts (fp16, grouped)
    gemm_h<1><<<dim3(II / 128, TT / 128, NEXP), 256, SMEM_H>>>(y, wegT, gg, TT, II, HHD, nullptr);
    gemm_h<1><<<dim3(II / 128, TT / 128, NEXP), 256, SMEM_H>>>(y, weuT, uu, TT, II, HHD, nullptr);
    silu_kernel<<<(TT * II) / 256, 256>>>(gg, uu);
    gemm_h<2><<<dim3(HHD / 128, TT / 128, NEXP), 256, SMEM_H>>>(gg, wedT, out, TT, HHD, II, nullptr);
}

// round 8
// speedup vs baseline: 2.8865x; 1.0818x over previous
#include <cuda_runtime.h>
#include <cuda_fp16.h>
#include <math.h>
#include <stdint.h>

#define TT     2048
#define HHD    2048
#define NHEADS 16
#define HDIM   128
#define QSZ    2048
#define KVSZ   512
#define QKVN   3072
#define NEXP   8
#define II     4096
#define EPSV   1e-5f

// ---------------- device scratch ----------------
__device__ __align__(256) float g_xn  [TT * HHD];
__device__ __align__(256) float g_qkv [TT * QKVN];
__device__ __align__(256) float g_att [TT * QSZ];
__device__ __align__(256) float g_x2  [TT * HHD];
__device__ __align__(256) float g_y   [TT * HHD];
__device__ __align__(256) float g_g   [TT * II];
__device__ __align__(256) float g_u   [TT * II];
__device__ int   g_expert[TT];
__device__ float g_gate  [TT];
__device__ int   g_cnt[NEXP];
__device__ int   g_off[NEXP];
__device__ int   g_cur[NEXP];
__device__ int   g_perm[TT];
// fp16 weight buffers (declared as float arrays, used as __half*)
__device__ __align__(256) float g_wqkvT [QKVN * HHD / 2];
__device__ __align__(256) float g_wqkvTl[QKVN * HHD / 2];
__device__ __align__(256) float g_woT   [HHD * QSZ / 2];
__device__ __align__(256) float g_woTl  [HHD * QSZ / 2];
__device__ __align__(256) float g_wsgT  [II * HHD / 2];
__device__ __align__(256) float g_wsuT  [II * HHD / 2];
__device__ __align__(256) float g_wsdT  [HHD * II / 2];
__device__ __align__(256) float g_wegT  [NEXP * II * HHD / 2];
__device__ __align__(256) float g_weuT  [NEXP * II * HHD / 2];
__device__ __align__(256) float g_wedT  [NEXP * HHD * II / 2];

#define LOSCALE 1024.0f
#define INVLOSCALE (1.0f / 1024.0f)

// ---------------- helpers ----------------
__device__ __forceinline__ uint32_t smem_u32(const void* p) {
    uint32_t a;
    asm("{ .reg .u64 t; cvta.to.shared.u64 t, %1; cvt.u32.u64 %0, t; }" : "=r"(a) : "l"(p));
    return a;
}
__device__ __forceinline__ uint32_t packh2(float a, float b) {
    __half2 h = __floats2half2_rn(a, b);
    return *(uint32_t*)&h;
}
__device__ __forceinline__ void cpa16(uint32_t dst, const void* src) {
    asm volatile("cp.async.cg.shared.global [%0], [%1], 16;" :: "r"(dst), "l"(src) : "memory");
}
#define CP_COMMIT() asm volatile("cp.async.commit_group;" ::: "memory")
#define CP_WAIT1()  asm volatile("cp.async.wait_group 1;" ::: "memory")
#define CP_WAIT0()  asm volatile("cp.async.wait_group 0;" ::: "memory")

#define MMA_F16(d, a, b0, b1) \
  asm volatile("mma.sync.aligned.m16n8k16.row.col.f32.f16.f16.f32 " \
    "{%0,%1,%2,%3}, {%4,%5,%6,%7}, {%8,%9}, {%0,%1,%2,%3};" \
    : "+f"((d)[0]), "+f"((d)[1]), "+f"((d)[2]), "+f"((d)[3]) \
    : "r"((a)[0]), "r"((a)[1]), "r"((a)[2]), "r"((a)[3]), "r"(b0), "r"(b1))

// ---------------- transposes (stride-68 smem, vectorized both sides) ----------------
__global__ __launch_bounds__(256) void transpose_f16(
    const float* __restrict__ in, __half* __restrict__ out, int R, int C)
{
    __shared__ float t[64 * 68];
    in  += (size_t)blockIdx.z * (size_t)R * C;
    out += (size_t)blockIdx.z * (size_t)R * C;
    int c0 = blockIdx.x * 64, r0 = blockIdx.y * 64;
#pragma unroll
    for (int it = 0; it < 4; it++) {
        int idx = threadIdx.x + 256 * it;
        int r = idx >> 4, cq = (idx & 15) << 2;
        float4 v = *(const float4*)&in[(size_t)(r0 + r) * C + c0 + cq];
        t[(cq + 0) * 68 + r] = v.x;
        t[(cq + 1) * 68 + r] = v.y;
        t[(cq + 2) * 68 + r] = v.z;
        t[(cq + 3) * 68 + r] = v.w;
    }
    __syncthreads();
#pragma unroll
    for (int it = 0; it < 4; it++) {
        int idx = threadIdx.x + 256 * it;
        int c = idx >> 4, q = (idx & 15) << 2;
        float4 x = *(const float4*)&t[c * 68 + q];
        uint2 v;
        v.x = packh2(x.x, x.y);
        v.y = packh2(x.z, x.w);
        *(uint2*)&out[(size_t)(c0 + c) * R + r0 + q] = v;
    }
}

// fp16 hi/lo split: hi = h(x), lo = h((x - hi) * 1024)
__global__ __launch_bounds__(256) void transpose_split_h(
    const float* __restrict__ in, __half* __restrict__ hi, __half* __restrict__ lo,
    int R, int C)
{
    __shared__ float t[64 * 68];
    int c0 = blockIdx.x * 64, r0 = blockIdx.y * 64;
#pragma unroll
    for (int it = 0; it < 4; it++) {
        int idx = threadIdx.x + 256 * it;
        int r = idx >> 4, cq = (idx & 15) << 2;
        float4 v = *(const float4*)&in[(size_t)(r0 + r) * C + c0 + cq];
        t[(cq + 0) * 68 + r] = v.x;
        t[(cq + 1) * 68 + r] = v.y;
        t[(cq + 2) * 68 + r] = v.z;
        t[(cq + 3) * 68 + r] = v.w;
    }
    __syncthreads();
#pragma unroll
    for (int it = 0; it < 4; it++) {
        int idx = threadIdx.x + 256 * it;
        int c = idx >> 4, q = (idx & 15) << 2;
        float4 x = *(const float4*)&t[c * 68 + q];
        float h0 = __half2float(__float2half_rn(x.x));
        float h1 = __half2float(__float2half_rn(x.y));
        float h2 = __half2float(__float2half_rn(x.z));
        float h3 = __half2float(__float2half_rn(x.w));
        uint2 vh, vl;
        vh.x = packh2(x.x, x.y);
        vh.y = packh2(x.z, x.w);
        vl.x = packh2((x.x - h0) * LOSCALE, (x.y - h1) * LOSCALE);
        vl.y = packh2((x.z - h2) * LOSCALE, (x.w - h3) * LOSCALE);
        size_t o = (size_t)(c0 + c) * R + r0 + q;
        *(uint2*)&hi[o] = vh;
        *(uint2*)&lo[o] = vl;
    }
}

// ---------------- fp16 GEMM (plain): C = A@B ----------------
#define HSTR 20
#define HTILE (128 * HSTR)
#define HSTG  (2 * HTILE)
#define SMEM_H (2 * HSTG * 4)

template<int MODE>
__global__ void __launch_bounds__(256) gemm_h(
    const float* __restrict__ A, const __half* __restrict__ BT,
    float* __restrict__ C, int M, int N, int K, const float* __restrict__ Res)
{
    int e = blockIdx.z;
    int cnt = M, base = 0;
    if (MODE) {
        cnt = g_cnt[e]; base = g_off[e];
        if ((int)blockIdx.y * 128 >= cnt) return;
        BT += (size_t)e * (size_t)N * K;
    }
    int bm = blockIdx.y * 128, bn = blockIdx.x * 128;
    int tid = threadIdx.x, lane = tid & 31, warp = tid >> 5;
    int wm = warp & 3, wn = warp >> 2;
    int g = lane >> 2, tig = lane & 3;

    extern __shared__ __align__(16) float smf[];
    uint32_t smb = smem_u32(smf);
    const uint32_t* SM = (const uint32_t*)smf;

    const float* aptr[2]; const __half* bptr[2];
    uint32_t aoff[2], boff[2];
#pragma unroll
    for (int i = 0; i < 2; i++) {
        int idx = tid + 256 * i;
        int r = idx >> 2, cg = idx & 3;
        int row;
        if (MODE == 1) { int rr = bm + r; if (rr >= cnt) rr = cnt - 1; row = g_perm[base + rr]; }
        else if (MODE == 2) { int rr = bm + r; if (rr >= cnt) rr = cnt - 1; row = base + rr; }
        else row = bm + r;
        aptr[i] = A + (size_t)row * K + cg * 8;
        bptr[i] = BT + (size_t)(bn + r) * K + cg * 8;
        aoff[i] = (uint32_t)(r * HSTR + cg * 4) * 4;
        boff[i] = (uint32_t)(HTILE + r * HSTR + cg * 4) * 4;
    }

    float4 areg[2][2];
#pragma unroll
    for (int i = 0; i < 2; i++) {
        areg[i][0] = *(const float4*)(aptr[i]);
        areg[i][1] = *(const float4*)(aptr[i] + 4);
        cpa16(smb + boff[i], bptr[i]);
    }
    CP_COMMIT();
#pragma unroll
    for (int i = 0; i < 2; i++) {
        uint32_t w0 = packh2(areg[i][0].x, areg[i][0].y);
        uint32_t w1 = packh2(areg[i][0].z, areg[i][0].w);
        uint32_t w2 = packh2(areg[i][1].x, areg[i][1].y);
        uint32_t w3 = packh2(areg[i][1].z, areg[i][1].w);
        asm volatile("st.shared.v4.b32 [%0], {%1,%2,%3,%4};"
                     :: "r"(smb + aoff[i]), "r"(w0), "r"(w1), "r"(w2), "r"(w3) : "memory");
    }

    float acc[2][8][4];
#pragma unroll
    for (int mt = 0; mt < 2; mt++)
#pragma unroll
        for (int nt = 0; nt < 8; nt++)
#pragma unroll
            for (int q = 0; q < 4; q++) acc[mt][nt][q] = 0.f;

    const int abase = (wm * 32 + g) * HSTR + tig;
    const int bbase = (wn * 64 + g) * HSTR + tig;
    const int KC = K / 32;

    for (int c = 0; c < KC; c++) {
        int s = c & 1;
        bool more = (c + 1 < KC);
        if (more) {
            uint32_t nb = smb + (uint32_t)(s ^ 1) * HSTG * 4;
#pragma unroll
            for (int i = 0; i < 2; i++) {
                areg[i][0] = *(const float4*)(aptr[i] + (c + 1) * 32);
                areg[i][1] = *(const float4*)(aptr[i] + (c + 1) * 32 + 4);
                cpa16(nb + boff[i], bptr[i] + (c + 1) * 32);
            }
            CP_COMMIT();
            CP_WAIT1();
        } else {
            CP_WAIT0();
        }
        __syncthreads();

        const uint32_t* AH = SM + s * HSTG;
        const uint32_t* BH = AH + HTILE;

#pragma unroll
        for (int ks = 0; ks < 2; ks++) {
            uint32_t ah[2][4];
#pragma unroll
            for (int mt = 0; mt < 2; mt++) {
                int a0 = abase + mt * 16 * HSTR + ks * 8;
                ah[mt][0] = AH[a0];
                ah[mt][1] = AH[a0 + 8 * HSTR];
                ah[mt][2] = AH[a0 + 4];
                ah[mt][3] = AH[a0 + 8 * HSTR + 4];
            }
#pragma unroll
            for (int nt = 0; nt < 8; nt++) {
                int b0i = bbase + nt * 8 * HSTR + ks * 8;
                uint32_t b0 = BH[b0i], b1 = BH[b0i + 4];
#pragma unroll
                for (int mt = 0; mt < 2; mt++)
                    MMA_F16(acc[mt][nt], ah[mt], b0, b1);
            }
        }
        __syncthreads();

        if (more) {
            uint32_t nb = smb + (uint32_t)(s ^ 1) * HSTG * 4;
#pragma unroll
            for (int i = 0; i < 2; i++) {
                uint32_t w0 = packh2(areg[i][0].x, areg[i][0].y);
                uint32_t w1 = packh2(areg[i][0].z, areg[i][0].w);
                uint32_t w2 = packh2(areg[i][1].x, areg[i][1].y);
                uint32_t w3 = packh2(areg[i][1].z, areg[i][1].w);
                asm volatile("st.shared.v4.b32 [%0], {%1,%2,%3,%4};"
                             :: "r"(nb + aoff[i]), "r"(w0), "r"(w1), "r"(w2), "r"(w3) : "memory");
            }
        }
    }

#pragma unroll
    for (int mt = 0; mt < 2; mt++) {
        int mloc0 = wm * 32 + mt * 16 + g;
#pragma unroll
        for (int nt = 0; nt < 8; nt++) {
            int col = bn + wn * 64 + nt * 8 + 2 * tig;
            float* d = acc[mt][nt];
            if (MODE == 0) {
                size_t i0 = (size_t)(bm + mloc0) * N + col;
                size_t i1 = (size_t)(bm + mloc0 + 8) * N + col;
                float2 v0 = make_float2(d[0], d[1]);
                float2 v1 = make_float2(d[2], d[3]);
                if (Res) {
                    float2 r0 = *(const float2*)&Res[i0];
                    float2 r1 = *(const float2*)&Res[i1];
                    v0.x += r0.x; v0.y += r0.y; v1.x += r1.x; v1.y += r1.y;
                }
                *(float2*)&C[i0] = v0;
                *(float2*)&C[i1] = v1;
            } else if (MODE == 1) {
                if (bm + mloc0 < cnt) {
                    size_t i0 = (size_t)(base + bm + mloc0) * N + col;
                    *(float2*)&C[i0] = make_float2(d[0], d[1]);
                }
                if (bm + mloc0 + 8 < cnt) {
                    size_t i1 = (size_t)(base + bm + mloc0 + 8) * N + col;
                    *(float2*)&C[i1] = make_float2(d[2], d[3]);
                }
            } else {
                if (bm + mloc0 < cnt) {
                    int tok = g_perm[base + bm + mloc0];
                    float gt = g_gate[tok];
                    size_t i0 = (size_t)tok * N + col;
                    float2 o = *(const float2*)&C[i0];
                    o.x += gt * d[0]; o.y += gt * d[1];
                    *(float2*)&C[i0] = o;
                }
                if (bm + mloc0 + 8 < cnt) {
                    int tok = g_perm[base + bm + mloc0 + 8];
                    float gt = g_gate[tok];
                    size_t i1 = (size_t)tok * N + col;
                    float2 o = *(const float2*)&C[i1];
                    o.x += gt * d[2]; o.y += gt * d[3];
                    *(float2*)&C[i1] = o;
                }
            }
        }
    }
}

// ---------------- double-fp16 compensated GEMM (router-upstream paths) ----------------
// x ≈ hi + lo/1024 (hi,lo fp16). acc1 = Σ ahi·bhi; acc2 = Σ ahi·blo + alo·bhi.
// C = acc1 + acc2/1024 (+Res).
#define HCSTG (4 * HTILE)            // Ahi, Bhi, Alo, Blo
#define SMEM_HC (2 * HCSTG * 4)      // 81920 bytes

__global__ void __launch_bounds__(256) gemm_hc(
    const float* __restrict__ A, const __half* __restrict__ BHI,
    const __half* __restrict__ BLO, float* __restrict__ C,
    int M, int N, int K, const float* __restrict__ Res)
{
    int bm = blockIdx.y * 128, bn = blockIdx.x * 128;
    int tid = threadIdx.x, lane = tid & 31, warp = tid >> 5;
    int wm = warp & 3, wn = warp >> 2;
    int g = lane >> 2, tig = lane & 3;

    extern __shared__ __align__(16) float smf[];
    uint32_t smb = smem_u32(smf);
    const uint32_t* SM = (const uint32_t*)smf;

    const float* aptr[2]; const __half* bhp[2]; const __half* blp[2];
    uint32_t aoff[2], boff[2];
#pragma unroll
    for (int i = 0; i < 2; i++) {
        int idx = tid + 256 * i;
        int r = idx >> 2, cg = idx & 3;
        aptr[i] = A + (size_t)(bm + r) * K + cg * 8;
        bhp[i]  = BHI + (size_t)(bn + r) * K + cg * 8;
        blp[i]  = BLO + (size_t)(bn + r) * K + cg * 8;
        aoff[i] = (uint32_t)(r * HSTR + cg * 4) * 4;
        boff[i] = (uint32_t)(HTILE + r * HSTR + cg * 4) * 4;
    }

    float4 areg[2][2];
#pragma unroll
    for (int i = 0; i < 2; i++) {
        areg[i][0] = *(const float4*)(aptr[i]);
        areg[i][1] = *(const float4*)(aptr[i] + 4);
        cpa16(smb + boff[i], bhp[i]);
        cpa16(smb + 2 * HTILE * 4 + boff[i], blp[i]);   // Blo at 3*HTILE (boff already includes +HTILE)
    }
    CP_COMMIT();
#pragma unroll
    for (int i = 0; i < 2; i++) {
        float x0 = areg[i][0].x, x1 = areg[i][0].y, x2 = areg[i][0].z, x3 = areg[i][0].w;
        float x4 = areg[i][1].x, x5 = areg[i][1].y, x6 = areg[i][1].z, x7 = areg[i][1].w;
        float h0 = __half2float(__float2half_rn(x0)), h1 = __half2float(__float2half_rn(x1));
        float h2 = __half2float(__float2half_rn(x2)), h3 = __half2float(__float2half_rn(x3));
        float h4 = __half2float(__float2half_rn(x4)), h5 = __half2float(__float2half_rn(x5));
        float h6 = __half2float(__float2half_rn(x6)), h7 = __half2float(__float2half_rn(x7));
        uint32_t a0 = packh2(x0, x1), a1 = packh2(x2, x3), a2 = packh2(x4, x5), a3 = packh2(x6, x7);
        uint32_t l0 = packh2((x0 - h0) * LOSCALE, (x1 - h1) * LOSCALE);
        uint32_t l1 = packh2((x2 - h2) * LOSCALE, (x3 - h3) * LOSCALE);
        uint32_t l2 = packh2((x4 - h4) * LOSCALE, (x5 - h5) * LOSCALE);
        uint32_t l3 = packh2((x6 - h6) * LOSCALE, (x7 - h7) * LOSCALE);
        asm volatile("st.shared.v4.b32 [%0], {%1,%2,%3,%4};"
                     :: "r"(smb + aoff[i]), "r"(a0), "r"(a1), "r"(a2), "r"(a3) : "memory");
        asm volatile("st.shared.v4.b32 [%0], {%1,%2,%3,%4};"
                     :: "r"(smb + 2 * HTILE * 4 + aoff[i]), "r"(l0), "r"(l1), "r"(l2), "r"(l3) : "memory");
    }

    float acc1[2][8][4], acc2[2][8][4];
#pragma unroll
    for (int mt = 0; mt < 2; mt++)
#pragma unroll
        for (int nt = 0; nt < 8; nt++)
#pragma unroll
            for (int q = 0; q < 4; q++) { acc1[mt][nt][q] = 0.f; acc2[mt][nt][q] = 0.f; }

    const int abase = (wm * 32 + g) * HSTR + tig;
    const int bbase = (wn * 64 + g) * HSTR + tig;
    const int KC = K / 32;

    for (int c = 0; c < KC; c++) {
        int s = c & 1;
        bool more = (c + 1 < KC);
        if (more) {
            uint32_t nb = smb + (uint32_t)(s ^ 1) * HCSTG * 4;
#pragma unroll
            for (int i = 0; i < 2; i++) {
                areg[i][0] = *(const float4*)(aptr[i] + (c + 1) * 32);
                areg[i][1] = *(const float4*)(aptr[i] + (c + 1) * 32 + 4);
                cpa16(nb + boff[i], bhp[i] + (c + 1) * 32);
                cpa16(nb + 2 * HTILE * 4 + boff[i], blp[i] + (c + 1) * 32);
            }
            CP_COMMIT();
            CP_WAIT1();
        } else {
            CP_WAIT0();
        }
        __syncthreads();

        const uint32_t* AH = SM + s * HCSTG;           // Ahi
        const uint32_t* BH = AH + HTILE;               // Bhi
        const uint32_t* AL = AH + 2 * HTILE;           // Alo
        const uint32_t* BL = AH + 3 * HTILE;           // Blo

#pragma unroll
        for (int ks = 0; ks < 2; ks++) {
            uint32_t ah[2][4], al[2][4];
#pragma unroll
            for (int mt = 0; mt < 2; mt++) {
                int a0 = abase + mt * 16 * HSTR + ks * 8;
                ah[mt][0] = AH[a0];            ah[mt][1] = AH[a0 + 8 * HSTR];
                ah[mt][2] = AH[a0 + 4];        ah[mt][3] = AH[a0 + 8 * HSTR + 4];
                al[mt][0] = AL[a0];            al[mt][1] = AL[a0 + 8 * HSTR];
                al[mt][2] = AL[a0 + 4];        al[mt][3] = AL[a0 + 8 * HSTR + 4];
            }
#pragma unroll
            for (int nt = 0; nt < 8; nt++) {
                int b0i = bbase + nt * 8 * HSTR + ks * 8;
                uint32_t b0 = BH[b0i], b1 = BH[b0i + 4];
                uint32_t c0 = BL[b0i], c1 = BL[b0i + 4];
#pragma unroll
                for (int mt = 0; mt < 2; mt++) {
                    MMA_F16(acc1[mt][nt], ah[mt], b0, b1);
                    MMA_F16(acc2[mt][nt], ah[mt], c0, c1);
                    MMA_F16(acc2[mt][nt], al[mt], b0, b1);
                }
            }
        }
        __syncthreads();

        if (more) {
            uint32_t nb = smb + (uint32_t)(s ^ 1) * HCSTG * 4;
#pragma unroll
            for (int i = 0; i < 2; i++) {
                float x0 = areg[i][0].x, x1 = areg[i][0].y, x2 = areg[i][0].z, x3 = areg[i][0].w;
                float x4 = areg[i][1].x, x5 = areg[i][1].y, x6 = areg[i][1].z, x7 = areg[i][1].w;
                float h0 = __half2float(__float2half_rn(x0)), h1 = __half2float(__float2half_rn(x1));
                float h2 = __half2float(__float2half_rn(x2)), h3 = __half2float(__float2half_rn(x3));
                float h4 = __half2float(__float2half_rn(x4)), h5 = __half2float(__float2half_rn(x5));
                float h6 = __half2float(__float2half_rn(x6)), h7 = __half2float(__float2half_rn(x7));
                uint32_t a0 = packh2(x0, x1), a1 = packh2(x2, x3), a2 = packh2(x4, x5), a3 = packh2(x6, x7);
                uint32_t l0 = packh2((x0 - h0) * LOSCALE, (x1 - h1) * LOSCALE);
                uint32_t l1 = packh2((x2 - h2) * LOSCALE, (x3 - h3) * LOSCALE);
                uint32_t l2 = packh2((x4 - h4) * LOSCALE, (x5 - h5) * LOSCALE);
                uint32_t l3 = packh2((x6 - h6) * LOSCALE, (x7 - h7) * LOSCALE);
                asm volatile("st.shared.v4.b32 [%0], {%1,%2,%3,%4};"
                             :: "r"(nb + aoff[i]), "r"(a0), "r"(a1), "r"(a2), "r"(a3) : "memory");
                asm volatile("st.shared.v4.b32 [%0], {%1,%2,%3,%4};"
                             :: "r"(nb + 2 * HTILE * 4 + aoff[i]), "r"(l0), "r"(l1), "r"(l2), "r"(l3) : "memory");
            }
        }
    }

#pragma unroll
    for (int mt = 0; mt < 2; mt++) {
        int mloc0 = wm * 32 + mt * 16 + g;
#pragma unroll
        for (int nt = 0; nt < 8; nt++) {
            int col = bn + wn * 64 + nt * 8 + 2 * tig;
            float* d1 = acc1[mt][nt];
            float* d2 = acc2[mt][nt];
            size_t i0 = (size_t)(bm + mloc0) * N + col;
            size_t i1 = (size_t)(bm + mloc0 + 8) * N + col;
            float2 v0 = make_float2(d1[0] + d2[0] * INVLOSCALE, d1[1] + d2[1] * INVLOSCALE);
            float2 v1 = make_float2(d1[2] + d2[2] * INVLOSCALE, d1[3] + d2[3] * INVLOSCALE);
            if (Res) {
                float2 r0 = *(const float2*)&Res[i0];
                float2 r1 = *(const float2*)&Res[i1];
                v0.x += r0.x; v0.y += r0.y; v1.x += r1.x; v1.y += r1.y;
            }
            *(float2*)&C[i0] = v0;
            *(float2*)&C[i1] = v1;
        }
    }
}

// ---------------- rmsnorm ----------------
__global__ __launch_bounds__(256) void rmsnorm_kernel(
    const float* __restrict__ x, const float* __restrict__ w, float* __restrict__ o)
{
    int t = blockIdx.x, tid = threadIdx.x;
    const float* r = x + (size_t)t * HHD;
    float ss = 0.f;
    for (int j = tid; j < HHD; j += 256) { float v = r[j]; ss += v * v; }
    __shared__ float red[256];
    red[tid] = ss; __syncthreads();
    for (int s = 128; s > 0; s >>= 1) { if (tid < s) red[tid] += red[tid + s]; __syncthreads(); }
    float scale = rsqrtf(red[0] / (float)HHD + EPSV);
    float* out = o + (size_t)t * HHD;
    for (int j = tid; j < HHD; j += 256) out[j] = r[j] * scale * w[j];
}

// ---------------- rope + q/k rmsnorm ----------------
__global__ __launch_bounds__(256) void ropenorm_kernel(
    float* __restrict__ qkv, const int* __restrict__ pos,
    const float* __restrict__ qw, const float* __restrict__ kw)
{
    int t = blockIdx.x, tid = threadIdx.x;
    float* row = qkv + (size_t)t * QKVN;
    float p = (float)pos[t];
    const float lgt = logf(500000.0f);
    __shared__ float red[256];
    __shared__ float sq, sk;

    float ss = 0.f;
    for (int idx = tid; idx < 1024; idx += 256) {
        int hh = idx >> 6, i = idx & 63;
        float inv = expf(-lgt * (float)i * (1.0f / 64.0f));
        float fr = p * inv, c = cosf(fr), s = sinf(fr);
        float x1 = row[hh * 128 + i], x2 = row[hh * 128 + 64 + i];
        float o1 = x1 * c - x2 * s, o2 = x2 * c + x1 * s;
        row[hh * 128 + i] = o1; row[hh * 128 + 64 + i] = o2;
        ss += o1 * o1 + o2 * o2;
    }
    red[tid] = ss; __syncthreads();
    for (int s2 = 128; s2 > 0; s2 >>= 1) { if (tid < s2) red[tid] += red[tid + s2]; __syncthreads(); }
    if (tid == 0) sq = rsqrtf(red[0] / (float)QSZ + EPSV);
    __syncthreads();

    float ssk = 0.f;
    {
        int hh = tid >> 6, i = tid & 63;
        float inv = expf(-lgt * (float)i * (1.0f / 64.0f));
        float fr = p * inv, c = cosf(fr), s = sinf(fr);
        float* kb = row + QSZ;
        float x1 = kb[hh * 128 + i], x2 = kb[hh * 128 + 64 + i];
        float o1 = x1 * c - x2 * s, o2 = x2 * c + x1 * s;
        kb[hh * 128 + i] = o1; kb[hh * 128 + 64 + i] = o2;
        ssk = o1 * o1 + o2 * o2;
    }
    red[tid] = ssk; __syncthreads();
    for (int s2 = 128; s2 > 0; s2 >>= 1) { if (tid < s2) red[tid] += red[tid + s2]; __syncthreads(); }
    if (tid == 0) sk = rsqrtf(red[0] / (float)KVSZ + EPSV);
    __syncthreads();

    for (int j = tid; j < QSZ; j += 256) row[j] *= sq * qw[j];
    for (int j = tid; j < KVSZ; j += 256) row[QSZ + j] *= sk * kw[j];
}

// ---------------- flash attention (fp32, float4-vectorized) ----------------
#define QKSTR 132
#define PSTR  68
#define SMEM_ATTN ((3 * 64 * QKSTR + 64 * PSTR) * 4)

__global__ __launch_bounds__(256) void attn_kernel(
    const float* __restrict__ qkv, float* __restrict__ O)
{
    extern __shared__ float sh[];
    float* Qs = sh;
    float* Ks = sh + 64 * QKSTR;
    float* Vs = sh + 2 * 64 * QKSTR;
    float* Ps = sh + 3 * 64 * QKSTR;

    int m0 = ((int)gridDim.x - 1 - (int)blockIdx.x) * 64;
    int h  = blockIdx.y;
    int kvh = h >> 2;
    int tid = threadIdx.x, lane = tid & 31, w = tid >> 5;
    const float scl = 0.08838834764831845f;

    for (int i = tid; i < 2048; i += 256) {
        int r = i >> 5, c = (i & 31) << 2;
        *(float4*)&Qs[r * QKSTR + c] =
            *(const float4*)&qkv[(size_t)(m0 + r) * QKVN + h * HDIM + c];
    }

    float mrow[8], lrow[8], oacc[8][4];
#pragma unroll
    for (int r = 0; r < 8; r++) {
        mrow[r] = -1e30f; lrow[r] = 0.f;
        oacc[r][0] = oacc[r][1] = oacc[r][2] = oacc[r][3] = 0.f;
    }
    int d0 = lane << 2;

    for (int n0 = 0; n0 <= m0; n0 += 64) {
        __syncthreads();
        for (int i = tid; i < 2048; i += 256) {
            int r = i >> 5, c = (i & 31) << 2;
            *(float4*)&Ks[r * QKSTR + c] =
                *(const float4*)&qkv[(size_t)(n0 + r) * QKVN + QSZ + kvh * HDIM + c];
            *(float4*)&Vs[r * QKSTR + c] =
                *(const float4*)&qkv[(size_t)(n0 + r) * QKVN + QSZ + KVSZ + kvh * HDIM + c];
        }
        __syncthreads();

        float s0[8] = {0,0,0,0,0,0,0,0};
        float s1[8] = {0,0,0,0,0,0,0,0};
#pragma unroll 4
        for (int k = 0; k < 128; k += 4) {
            float4 k0 = *(float4*)&Ks[lane * QKSTR + k];
            float4 k1 = *(float4*)&Ks[(lane + 32) * QKSTR + k];
#pragma unroll
            for (int r = 0; r < 8; r++) {
                float4 q = *(float4*)&Qs[(w * 8 + r) * QKSTR + k];
                s0[r] += q.x * k0.x + q.y * k0.y + q.z * k0.z + q.w * k0.w;
                s1[r] += q.x * k1.x + q.y * k1.y + q.z * k1.z + q.w * k1.w;
            }
        }
        bool diag = (n0 + 63 > m0);
#pragma unroll
        for (int r = 0; r < 8; r++) {
            int grow = m0 + w * 8 + r;
            float v0 = s0[r] * scl, v1 = s1[r] * scl;
            if (diag) {
                if (n0 + lane      > grow) v0 = -1e30f;
                if (n0 + lane + 32 > grow) v1 = -1e30f;
            }
            float tmax = fmaxf(v0, v1);
#pragma unroll
            for (int o = 16; o; o >>= 1) tmax = fmaxf(tmax, __shfl_xor_sync(~0u, tmax, o));
            float nm = fmaxf(mrow[r], tmax);
            float p0 = __expf(v0 - nm), p1 = __expf(v1 - nm);
            float corr = __expf(mrow[r] - nm);
            float psum = p0 + p1;
#pragma unroll
            for (int o = 16; o; o >>= 1) psum += __shfl_xor_sync(~0u, psum, o);
            lrow[r] = lrow[r] * corr + psum;
            mrow[r] = nm;
            oacc[r][0] *= corr; oacc[r][1] *= corr; oacc[r][2] *= corr; oacc[r][3] *= corr;
            Ps[(w * 8 + r) * PSTR + lane]      = p0;
            Ps[(w * 8 + r) * PSTR + lane + 32] = p1;
        }
        __syncwarp();
#pragma unroll 2
        for (int n = 0; n < 64; n += 4) {
            float4 v0 = *(float4*)&Vs[(n + 0) * QKSTR + d0];
            float4 v1 = *(float4*)&Vs[(n + 1) * QKSTR + d0];
            float4 v2 = *(float4*)&Vs[(n + 2) * QKSTR + d0];
            float4 v3 = *(float4*)&Vs[(n + 3) * QKSTR + d0];
#pragma unroll
            for (int r = 0; r < 8; r++) {
                float4 pv = *(float4*)&Ps[(w * 8 + r) * PSTR + n];
                oacc[r][0] += pv.x * v0.x + pv.y * v1.x + pv.z * v2.x + pv.w * v3.x;
                oacc[r][1] += pv.x * v0.y + pv.y * v1.y + pv.z * v2.y + pv.w * v3.y;
                oacc[r][2] += pv.x * v0.z + pv.y * v1.z + pv.z * v2.z + pv.w * v3.z;
                oacc[r][3] += pv.x * v0.w + pv.y * v1.w + pv.z * v2.w + pv.w * v3.w;
            }
        }
    }
#pragma unroll
    for (int r = 0; r < 8; r++) {
        float inv = 1.0f / lrow[r];
        float4 o = make_float4(oacc[r][0] * inv, oacc[r][1] * inv,
                               oacc[r][2] * inv, oacc[r][3] * inv);
        *(float4*)&O[(size_t)(m0 + w * 8 + r) * QSZ + h * HDIM + d0] = o;
    }
}

// ---------------- router / permutation ----------------
__global__ void zero_kernel()
{
    int i = threadIdx.x;
    if (i < NEXP) { g_cnt[i] = 0; g_cur[i] = 0; }
}

__global__ __launch_bounds__(256) void router_kernel(
    const float* __restrict__ y, const float* __restrict__ rw)
{
    int t = blockIdx.x, tid = threadIdx.x;
    const float* x = y + (size_t)t * HHD;
    float part[NEXP] = {};
    for (int k = tid; k < HHD; k += 256) {
        float xv = x[k];
        const float* r = rw + (size_t)k * NEXP;
#pragma unroll
        for (int e = 0; e < NEXP; e++) part[e] += xv * r[e];
    }
    __shared__ float red[256];
    __shared__ float logit[NEXP];
    for (int e = 0; e < NEXP; e++) {
        red[tid] = part[e]; __syncthreads();
        for (int s = 128; s > 0; s >>= 1) { if (tid < s) red[tid] += red[tid + s]; __syncthreads(); }
        if (tid == 0) logit[e] = red[0];
        __syncthreads();
    }
    if (tid == 0) {
        int am = 0; float mv = logit[0];
        for (int e = 1; e < NEXP; e++) if (logit[e] > mv) { mv = logit[e]; am = e; }
        g_expert[t] = am;
        g_gate[t]   = 1.0f / (1.0f + expf(-mv));
        atomicAdd(&g_cnt[am], 1);
    }
}

__global__ void scan_kernel()
{
    int s = 0;
    for (int e = 0; e < NEXP; e++) { g_off[e] = s; s += g_cnt[e]; }
}

__global__ void scatter_kernel()
{
    int t = blockIdx.x * 256 + threadIdx.x;
    if (t >= TT) return;
    int e = g_expert[t];
    int p = atomicAdd(&g_cur[e], 1);
    g_perm[g_off[e] + p] = t;
}

// ---------------- silu ----------------
__global__ __launch_bounds__(256) void silu_kernel(float* __restrict__ g, const float* __restrict__ u)
{
    int i = blockIdx.x * 256 + threadIdx.x;
    float x = g[i];
    g[i] = (x / (1.0f + __expf(-x))) * u[i];
}

// ---------------- launcher ----------------
extern "C" void kernel_launch(void* const* d_in, const int* in_sizes, int n_in,
                              void* d_out, int out_size)
{
    const int*   positions = (const int*)  d_in[0];
    const float* hidden    = (const float*)d_in[1];
    const float* ln1       = (const float*)d_in[2];
    const float* ln2       = (const float*)d_in[3];
    const float* w_qkv     = (const float*)d_in[4];
    const float* w_o       = (const float*)d_in[5];
    const float* qnw       = (const float*)d_in[6];
    const float* knw       = (const float*)d_in[7];
    const float* rw        = (const float*)d_in[8];
    const float* wsg       = (const float*)d_in[9];
    const float* wsu       = (const float*)d_in[10];
    const float* wsd       = (const float*)d_in[11];
    const float* weg       = (const float*)d_in[12];
    const float* weu       = (const float*)d_in[13];
    const float* wed       = (const float*)d_in[14];
    float* out = (float*)d_out;

    void* p;
    cudaGetSymbolAddress(&p, g_xn);  float* xn  = (float*)p;
    cudaGetSymbolAddress(&p, g_qkv); float* qkv = (float*)p;
    cudaGetSymbolAddress(&p, g_att); float* att = (float*)p;
    cudaGetSymbolAddress(&p, g_x2);  float* x2  = (float*)p;
    cudaGetSymbolAddress(&p, g_y);   float* y   = (float*)p;
    cudaGetSymbolAddress(&p, g_g);   float* gg  = (float*)p;
    cudaGetSymbolAddress(&p, g_u);   float* uu  = (float*)p;
    cudaGetSymbolAddress(&p, g_wqkvT);  __half* wqkvT  = (__half*)p;
    cudaGetSymbolAddress(&p, g_wqkvTl); __half* wqkvTl = (__half*)p;
    cudaGetSymbolAddress(&p, g_woT);    __half* woT    = (__half*)p;
    cudaGetSymbolAddress(&p, g_woTl);   __half* woTl   = (__half*)p;
    cudaGetSymbolAddress(&p, g_wsgT);   __half* wsgT   = (__half*)p;
    cudaGetSymbolAddress(&p, g_wsuT);   __half* wsuT   = (__half*)p;
    cudaGetSymbolAddress(&p, g_wsdT);   __half* wsdT   = (__half*)p;
    cudaGetSymbolAddress(&p, g_wegT);   __half* wegT   = (__half*)p;
    cudaGetSymbolAddress(&p, g_weuT);   __half* weuT   = (__half*)p;
    cudaGetSymbolAddress(&p, g_wedT);   __half* wedT   = (__half*)p;

    cudaFuncSetAttribute(attn_kernel, cudaFuncAttributeMaxDynamicSharedMemorySize, SMEM_ATTN);
    cudaFuncSetAttribute(gemm_hc, cudaFuncAttributeMaxDynamicSharedMemorySize, SMEM_HC);
    cudaFuncSetAttribute(gemm_h<0>, cudaFuncAttributeMaxDynamicSharedMemorySize, SMEM_H);
    cudaFuncSetAttribute(gemm_h<1>, cudaFuncAttributeMaxDynamicSharedMemorySize, SMEM_H);
    cudaFuncSetAttribute(gemm_h<2>, cudaFuncAttributeMaxDynamicSharedMemorySize, SMEM_H);

    // weight prep
    transpose_split_h<<<dim3(QKVN / 64, HHD / 64), 256>>>(w_qkv, wqkvT, wqkvTl, HHD, QKVN);
    transpose_split_h<<<dim3(HHD / 64, QSZ / 64), 256>>>(w_o, woT, woTl, QSZ, HHD);
    transpose_f16<<<dim3(II / 64, HHD / 64), 256>>>(wsg, wsgT, HHD, II);
    transpose_f16<<<dim3(II / 64, HHD / 64), 256>>>(wsu, wsuT, HHD, II);
    transpose_f16<<<dim3(HHD / 64, II / 64), 256>>>(wsd, wsdT, II, HHD);
    transpose_f16<<<dim3(II / 64, HHD / 64, NEXP), 256>>>(weg, wegT, HHD, II);
    transpose_f16<<<dim3(II / 64, HHD / 64, NEXP), 256>>>(weu, weuT, HHD, II);
    transpose_f16<<<dim3(HHD / 64, II / 64, NEXP), 256>>>(wed, wedT, II, HHD);

    // 1. x = rmsnorm(hidden, ln1)
    rmsnorm_kernel<<<TT, 256>>>(hidden, ln1, xn);
    // 2. qkv = x @ w_qkv   (double-fp16 compensated — upstream of router)
    gemm_hc<<<dim3(QKVN / 128, TT / 128), 256, SMEM_HC>>>(xn, wqkvT, wqkvTl, qkv, TT, QKVN, HHD, nullptr);
    // 3. rope + q/k norm
    ropenorm_kernel<<<TT, 256>>>(qkv, positions, qnw, knw);
    // 4. attention
    attn_kernel<<<dim3(TT / 64, NHEADS), 256, SMEM_ATTN>>>(qkv, att);
    // 5. x2 = hidden + attn @ w_o   (compensated)
    gemm_hc<<<dim3(HHD / 128, TT / 128), 256, SMEM_HC>>>(att, woT, woTl, x2, TT, HHD, QSZ, hidden);
    // 6. y = rmsnorm(x2, ln2)
    rmsnorm_kernel<<<TT, 256>>>(x2, ln2, y);
    // 7. router (fp32)
    zero_kernel<<<1, 32>>>();
    router_kernel<<<TT, 256>>>(y, rw);
    scan_kernel<<<1, 1>>>();
    scatter_kernel<<<TT / 256, 256>>>();
    // 8. shared expert (fp16)
    gemm_h<0><<<dim3(II / 128, TT / 128), 256, SMEM_H>>>(y, wsgT, gg, TT, II, HHD, nullptr);
    gemm_h<0><<<dim3(II / 128, TT / 128), 256, SMEM_H>>>(y, wsuT, uu, TT, II, HHD, nullptr);
    silu_kernel<<<(TT * II) / 256, 256>>>(gg, uu);
    gemm_h<0><<<dim3(HHD / 128, TT / 128), 256, SMEM_H>>>(gg, wsdT, out, TT, HHD, II, x2);
    // 9. routed experts (fp16, grouped)
    gemm_h<1><<<dim3(II / 128, TT / 128, NEXP), 256, SMEM_H>>>(y, wegT, gg, TT, II, HHD, nullptr);
    gemm_h<1><<<dim3(II / 128, TT / 128, NEXP), 256, SMEM_H>>>(y, weuT, uu, TT, II, HHD, nullptr);
    silu_kernel<<<(TT * II) / 256, 256>>>(gg, uu);
    gemm_h<2><<<dim3(HHD / 128, TT / 128, NEXP), 256, SMEM_H>>>(gg, wedT, out, TT, HHD, II, nullptr);
}